// round 1
// baseline (speedup 1.0000x reference)
#include <cuda_runtime.h>

// Problem constants
constexpr int NB = 8;     // batch
constexpr int SL = 2048;  // sequence length L
constexpr int ED = 128;   // embedding E

// GEMM tiling
constexpr int BM = 128, BN = 128, BK = 16, TM = 8, TN = 8;
constexpr int NTHREADS = 256;
constexpr int CCH = 8;    // column-sum chunks

// Scratch (device globals: allocation-free per harness rules)
__device__ float g_E[(size_t)NB * SL * SL];      // exp(S), 128 MiB
__device__ float g_c[NB * SL];                   // column sums of E
__device__ float g_cpart[NB * CCH * SL];
__device__ float g_sid[NB * SL];
__device__ float g_sq[NB * SL];
__device__ float g_Uqs[NB * SL * ED];            // Uq / c
__device__ float g_Ts[NB * SL * ED];             // (E^T Uid) / c^2
__device__ float g_AD2Q[NB * SL * ED];

// ---------------------------------------------------------------------------
// K1: s_id[b,i] = <Uid[b,i,:], w_id>, s_q[b,j] = <Uq[b,j,:], w_q>
// one warp per row, one float4 per lane (E=128 = 32 float4)
// ---------------------------------------------------------------------------
__global__ void scores_kernel(const float* __restrict__ Uq,
                              const float* __restrict__ Uid,
                              const float* __restrict__ Wc_w) {
    int gwarp = (blockIdx.x * blockDim.x + threadIdx.x) >> 5;
    int lane = threadIdx.x & 31;
    if (gwarp >= NB * SL) return;
    float4 a  = reinterpret_cast<const float4*>(Uid + (size_t)gwarp * ED)[lane];
    float4 w1 = reinterpret_cast<const float4*>(Wc_w)[lane];
    float4 b  = reinterpret_cast<const float4*>(Uq + (size_t)gwarp * ED)[lane];
    float4 w2 = reinterpret_cast<const float4*>(Wc_w + ED)[lane];
    float s1 = a.x * w1.x + a.y * w1.y + a.z * w1.z + a.w * w1.w;
    float s2 = b.x * w2.x + b.y * w2.y + b.z * w2.z + b.w * w2.w;
    #pragma unroll
    for (int o = 16; o > 0; o >>= 1) {
        s1 += __shfl_xor_sync(0xffffffffu, s1, o);
        s2 += __shfl_xor_sync(0xffffffffu, s2, o);
    }
    if (lane == 0) { g_sid[gwarp] = s1; g_sq[gwarp] = s2; }
}

// ---------------------------------------------------------------------------
// K2: E[b,i,j] = exp((s_mul + s_id + s_q + bias) * mask)
// NT GEMM: s_mul = (Uid .* w_mul) @ Uq^T,  K = 128, double buffered
// ---------------------------------------------------------------------------
__global__ void __launch_bounds__(NTHREADS)
e_kernel(const float* __restrict__ Uq, const float* __restrict__ Uid,
         const float* __restrict__ mask, const float* __restrict__ Wc_w,
         const float* __restrict__ Wc_b) {
    int b = blockIdx.z;
    int i0 = blockIdx.y * BM;
    int j0 = blockIdx.x * BN;
    const float* Ap = Uid + (size_t)b * SL * ED;
    const float* Bp = Uq + (size_t)b * SL * ED;
    const float* wm = Wc_w + 2 * ED;

    __shared__ float As[2][BK][BM];
    __shared__ float Bs[2][BK][BN];

    int tid = threadIdx.x;
    int tm = (tid & 15) * TM;
    int tn = (tid >> 4) * TN;
    float acc[TM][TN] = {};
    float4 ra[2], rb[2], rw[2];

    auto loadT = [&](int kk) {
        #pragma unroll
        for (int p = 0; p < 2; p++) {
            int f = tid + p * NTHREADS;
            int r = f >> 2;
            int c4 = (f & 3) * 4;
            ra[p] = *reinterpret_cast<const float4*>(Ap + (size_t)(i0 + r) * ED + kk + c4);
            rw[p] = *reinterpret_cast<const float4*>(wm + kk + c4);
            rb[p] = *reinterpret_cast<const float4*>(Bp + (size_t)(j0 + r) * ED + kk + c4);
        }
    };
    auto storeT = [&](int buf) {
        #pragma unroll
        for (int p = 0; p < 2; p++) {
            int f = tid + p * NTHREADS;
            int r = f >> 2;
            int c4 = (f & 3) * 4;
            As[buf][c4 + 0][r] = ra[p].x * rw[p].x;
            As[buf][c4 + 1][r] = ra[p].y * rw[p].y;
            As[buf][c4 + 2][r] = ra[p].z * rw[p].z;
            As[buf][c4 + 3][r] = ra[p].w * rw[p].w;
            Bs[buf][c4 + 0][r] = rb[p].x;
            Bs[buf][c4 + 1][r] = rb[p].y;
            Bs[buf][c4 + 2][r] = rb[p].z;
            Bs[buf][c4 + 3][r] = rb[p].w;
        }
    };

    constexpr int NT = ED / BK;  // 8
    loadT(0); storeT(0); __syncthreads();
    for (int t = 0; t < NT; t++) {
        int cur = t & 1;
        if (t + 1 < NT) loadT((t + 1) * BK);
        #pragma unroll
        for (int k = 0; k < BK; k++) {
            float av[TM], bv[TN];
            *reinterpret_cast<float4*>(av)     = *reinterpret_cast<float4*>(&As[cur][k][tm]);
            *reinterpret_cast<float4*>(av + 4) = *reinterpret_cast<float4*>(&As[cur][k][tm + 4]);
            *reinterpret_cast<float4*>(bv)     = *reinterpret_cast<float4*>(&Bs[cur][k][tn]);
            *reinterpret_cast<float4*>(bv + 4) = *reinterpret_cast<float4*>(&Bs[cur][k][tn + 4]);
            #pragma unroll
            for (int u = 0; u < TM; u++)
                #pragma unroll
                for (int v = 0; v < TN; v++)
                    acc[u][v] += av[u] * bv[v];
        }
        if (t + 1 < NT) { storeT(cur ^ 1); __syncthreads(); }
    }

    float bias = Wc_b[0];
    float* Eout = g_E + (size_t)b * SL * SL;
    #pragma unroll
    for (int u = 0; u < TM; u++) {
        int i = i0 + tm + u;
        float si = g_sid[b * SL + i] + bias;
        const float* mrow = mask + (size_t)i * SL;
        #pragma unroll
        for (int v = 0; v < TN; v += 4) {
            int j = j0 + tn + v;
            float4 mk = *reinterpret_cast<const float4*>(mrow + j);
            float4 sqv = *reinterpret_cast<const float4*>(&g_sq[b * SL + j]);
            float4 o;
            o.x = __expf((acc[u][v + 0] + si + sqv.x) * mk.x);
            o.y = __expf((acc[u][v + 1] + si + sqv.y) * mk.y);
            o.z = __expf((acc[u][v + 2] + si + sqv.z) * mk.z);
            o.w = __expf((acc[u][v + 3] + si + sqv.w) * mk.w);
            *reinterpret_cast<float4*>(Eout + (size_t)i * SL + j) = o;
        }
    }
}

// ---------------------------------------------------------------------------
// K3: column sums c[b,j] = sum_i E[b,i,j]  (two-stage, deterministic)
// ---------------------------------------------------------------------------
__global__ void colsum1_kernel() {
    int b = blockIdx.z, ch = blockIdx.y;
    int j = blockIdx.x * blockDim.x + threadIdx.x;
    const float* Ep = g_E + (size_t)b * SL * SL + j;
    int i0 = ch * (SL / CCH);
    float s0 = 0.f, s1 = 0.f, s2 = 0.f, s3 = 0.f;
    for (int i = i0; i < i0 + SL / CCH; i += 4) {
        s0 += Ep[(size_t)(i + 0) * SL];
        s1 += Ep[(size_t)(i + 1) * SL];
        s2 += Ep[(size_t)(i + 2) * SL];
        s3 += Ep[(size_t)(i + 3) * SL];
    }
    g_cpart[(b * CCH + ch) * SL + j] = (s0 + s1) + (s2 + s3);
}

__global__ void colsum2_kernel() {
    int idx = blockIdx.x * blockDim.x + threadIdx.x;
    int b = idx / SL, j = idx % SL;
    float s = 0.f;
    #pragma unroll
    for (int ch = 0; ch < CCH; ch++) s += g_cpart[(b * CCH + ch) * SL + j];
    g_c[idx] = s;
}

// K4: Uqs = Uq / c  (broadcast along e)
__global__ void scale_uq_kernel(const float* __restrict__ Uq) {
    int idx = blockIdx.x * blockDim.x + threadIdx.x;  // float4 index
    int row = idx / (ED / 4);
    float rc = 1.0f / g_c[row];
    float4 v = reinterpret_cast<const float4*>(Uq)[idx];
    v.x *= rc; v.y *= rc; v.z *= rc; v.w *= rc;
    reinterpret_cast<float4*>(g_Uqs)[idx] = v;
}

// ---------------------------------------------------------------------------
// NN GEMM: C[i,e] = sum_j E[i,j] * X[j,e]   (M=2048, N=128, K=2048)
// MODE 0: X = g_Uqs -> g_AD2Q
// MODE 1: X = g_Ts  -> A_Q2D; fused final assembly into d_out
// ---------------------------------------------------------------------------
template <int MODE>
__global__ void __launch_bounds__(NTHREADS)
gemm_nn_kernel(const float* __restrict__ Uid, float* __restrict__ outp) {
    int b = blockIdx.z;
    int i0 = blockIdx.y * BM;
    const float* Ap = g_E + (size_t)b * SL * SL;
    const float* Bp = (MODE == 0 ? g_Uqs : g_Ts) + (size_t)b * SL * ED;
    __shared__ float As[2][BK][BM];
    __shared__ float Bs[2][BK][BN];
    int tid = threadIdx.x;
    int tm = (tid & 15) * TM;
    int tn = (tid >> 4) * TN;
    float acc[TM][TN] = {};
    float4 ra[2], rb[2];

    auto loadT = [&](int kk) {
        #pragma unroll
        for (int p = 0; p < 2; p++) {
            int f = tid + p * NTHREADS;
            int rA = f >> 2, cA = (f & 3) * 4;
            ra[p] = *reinterpret_cast<const float4*>(Ap + (size_t)(i0 + rA) * SL + kk + cA);
            int rB = f >> 5, cB = (f & 31) * 4;
            rb[p] = *reinterpret_cast<const float4*>(Bp + (size_t)(kk + rB) * ED + cB);
        }
    };
    auto storeT = [&](int buf) {
        #pragma unroll
        for (int p = 0; p < 2; p++) {
            int f = tid + p * NTHREADS;
            int rA = f >> 2, cA = (f & 3) * 4;
            As[buf][cA + 0][rA] = ra[p].x;
            As[buf][cA + 1][rA] = ra[p].y;
            As[buf][cA + 2][rA] = ra[p].z;
            As[buf][cA + 3][rA] = ra[p].w;
            int rB = f >> 5, cB = (f & 31) * 4;
            *reinterpret_cast<float4*>(&Bs[buf][rB][cB]) = rb[p];
        }
    };

    constexpr int NT = SL / BK;  // 128
    loadT(0); storeT(0); __syncthreads();
    for (int t = 0; t < NT; t++) {
        int cur = t & 1;
        if (t + 1 < NT) loadT((t + 1) * BK);
        #pragma unroll
        for (int k = 0; k < BK; k++) {
            float av[TM], bv[TN];
            *reinterpret_cast<float4*>(av)     = *reinterpret_cast<float4*>(&As[cur][k][tm]);
            *reinterpret_cast<float4*>(av + 4) = *reinterpret_cast<float4*>(&As[cur][k][tm + 4]);
            *reinterpret_cast<float4*>(bv)     = *reinterpret_cast<float4*>(&Bs[cur][k][tn]);
            *reinterpret_cast<float4*>(bv + 4) = *reinterpret_cast<float4*>(&Bs[cur][k][tn + 4]);
            #pragma unroll
            for (int u = 0; u < TM; u++)
                #pragma unroll
                for (int v = 0; v < TN; v++)
                    acc[u][v] += av[u] * bv[v];
        }
        if (t + 1 < NT) { storeT(cur ^ 1); __syncthreads(); }
    }

    if (MODE == 0) {
        #pragma unroll
        for (int u = 0; u < TM; u++) {
            size_t rowo = ((size_t)b * SL + i0 + tm + u) * ED;
            #pragma unroll
            for (int v = 0; v < TN; v += 4) {
                float4 o = make_float4(acc[u][v], acc[u][v + 1], acc[u][v + 2], acc[u][v + 3]);
                *reinterpret_cast<float4*>(g_AD2Q + rowo + tn + v) = o;
            }
        }
    } else {
        #pragma unroll
        for (int u = 0; u < TM; u++) {
            size_t row = (size_t)b * SL + i0 + tm + u;
            const float* uidr = Uid + row * ED;
            const float* adr = g_AD2Q + row * ED;
            float* orow = outp + row * (4 * ED);
            #pragma unroll
            for (int v = 0; v < TN; v += 4) {
                int e = tn + v;
                float4 uv = *reinterpret_cast<const float4*>(uidr + e);
                float4 ad = *reinterpret_cast<const float4*>(adr + e);
                float4 aq = make_float4(acc[u][v], acc[u][v + 1], acc[u][v + 2], acc[u][v + 3]);
                *reinterpret_cast<float4*>(orow + e) = uv;
                *reinterpret_cast<float4*>(orow + ED + e) = ad;
                *reinterpret_cast<float4*>(orow + 2 * ED + e) =
                    make_float4(uv.x * ad.x, uv.y * ad.y, uv.z * ad.z, uv.w * ad.w);
                *reinterpret_cast<float4*>(orow + 3 * ED + e) =
                    make_float4(uv.x * aq.x, uv.y * aq.y, uv.z * aq.z, uv.w * aq.w);
            }
        }
    }
}

// ---------------------------------------------------------------------------
// TN GEMM: Ts[j,e] = (sum_i E[i,j] * Uid[i,e]) / c[j]^2
// ---------------------------------------------------------------------------
__global__ void __launch_bounds__(NTHREADS)
gemm_tn_kernel(const float* __restrict__ Uid) {
    int b = blockIdx.z;
    int j0 = blockIdx.y * BM;
    const float* Ap = g_E + (size_t)b * SL * SL;   // [i][j], contract over i
    const float* Bp = Uid + (size_t)b * SL * ED;   // [i][e]
    __shared__ float As[2][BK][BM];
    __shared__ float Bs[2][BK][BN];
    int tid = threadIdx.x;
    int tm = (tid & 15) * TM;
    int tn = (tid >> 4) * TN;
    float acc[TM][TN] = {};
    float4 ra[2], rb[2];

    auto loadT = [&](int kk) {
        #pragma unroll
        for (int p = 0; p < 2; p++) {
            int f = tid + p * NTHREADS;
            int r = f >> 5, c4 = (f & 31) * 4;
            ra[p] = *reinterpret_cast<const float4*>(Ap + (size_t)(kk + r) * SL + j0 + c4);
            rb[p] = *reinterpret_cast<const float4*>(Bp + (size_t)(kk + r) * ED + c4);
        }
    };
    auto storeT = [&](int buf) {
        #pragma unroll
        for (int p = 0; p < 2; p++) {
            int f = tid + p * NTHREADS;
            int r = f >> 5, c4 = (f & 31) * 4;
            *reinterpret_cast<float4*>(&As[buf][r][c4]) = ra[p];
            *reinterpret_cast<float4*>(&Bs[buf][r][c4]) = rb[p];
        }
    };

    constexpr int NT = SL / BK;  // 128
    loadT(0); storeT(0); __syncthreads();
    for (int t = 0; t < NT; t++) {
        int cur = t & 1;
        if (t + 1 < NT) loadT((t + 1) * BK);
        #pragma unroll
        for (int k = 0; k < BK; k++) {
            float av[TM], bv[TN];
            *reinterpret_cast<float4*>(av)     = *reinterpret_cast<float4*>(&As[cur][k][tm]);
            *reinterpret_cast<float4*>(av + 4) = *reinterpret_cast<float4*>(&As[cur][k][tm + 4]);
            *reinterpret_cast<float4*>(bv)     = *reinterpret_cast<float4*>(&Bs[cur][k][tn]);
            *reinterpret_cast<float4*>(bv + 4) = *reinterpret_cast<float4*>(&Bs[cur][k][tn + 4]);
            #pragma unroll
            for (int u = 0; u < TM; u++)
                #pragma unroll
                for (int v = 0; v < TN; v++)
                    acc[u][v] += av[u] * bv[v];
        }
        if (t + 1 < NT) { storeT(cur ^ 1); __syncthreads(); }
    }

    #pragma unroll
    for (int u = 0; u < TM; u++) {
        int j = j0 + tm + u;
        float cj = g_c[b * SL + j];
        float s = 1.0f / (cj * cj);
        size_t rowo = ((size_t)b * SL + j) * ED;
        #pragma unroll
        for (int v = 0; v < TN; v += 4) {
            float4 o = make_float4(acc[u][v] * s, acc[u][v + 1] * s,
                                   acc[u][v + 2] * s, acc[u][v + 3] * s);
            *reinterpret_cast<float4*>(g_Ts + rowo + tn + v) = o;
        }
    }
}

// ---------------------------------------------------------------------------
extern "C" void kernel_launch(void* const* d_in, const int* in_sizes, int n_in,
                              void* d_out, int out_size) {
    const float* Uq   = (const float*)d_in[0];
    const float* Uid  = (const float*)d_in[1];
    const float* mask = (const float*)d_in[2];
    const float* Wcw  = (const float*)d_in[3];
    const float* Wcb  = (const float*)d_in[4];
    float* out = (float*)d_out;

    scores_kernel<<<NB * SL / 8, 256>>>(Uq, Uid, Wcw);
    e_kernel<<<dim3(SL / BN, SL / BM, NB), NTHREADS>>>(Uq, Uid, mask, Wcw, Wcb);
    colsum1_kernel<<<dim3(SL / 256, CCH, NB), 256>>>();
    colsum2_kernel<<<NB * SL / 256, 256>>>();
    scale_uq_kernel<<<NB * SL * ED / 4 / 256, 256>>>(Uq);
    gemm_nn_kernel<0><<<dim3(1, SL / BM, NB), NTHREADS>>>(Uid, nullptr);  // A_D2Q
    gemm_tn_kernel<<<dim3(1, SL / BM, NB), NTHREADS>>>(Uid);              // Ts
    gemm_nn_kernel<1><<<dim3(1, SL / BM, NB), NTHREADS>>>(Uid, out);      // A_Q2D + assemble
}

// round 2
// speedup vs baseline: 2.3537x; 2.3537x over previous
#include <cuda_runtime.h>

constexpr int NB = 8, SL = 2048, ED = 128;
constexpr int BM = 128, BN = 128, BK = 16;
constexpr int NTH = 256;
constexpr int PAD_LD = 20;   // [m][k] ldmatrix layout row stride (floats): 80B -> conflict-free LDSM
constexpr int PAD_SC = 136;  // [k][n] scalar layout row stride: 136 mod 32 == 8 -> conflict-free LDS
constexpr int CCH = 8;

__device__ float g_E[(size_t)NB * SL * SL];
__device__ float g_c[NB * SL];
__device__ float g_cpart[NB * CCH * SL];
__device__ float g_sid[NB * SL];
__device__ float g_sq[NB * SL];
__device__ float g_Uqs[NB * SL * ED];
__device__ float g_Ts[NB * SL * ED];
__device__ float g_AD2Q[NB * SL * ED];

// ---------------------------------------------------------------------------
__device__ __forceinline__ unsigned f2tf(float f) {
    unsigned u;
    asm("cvt.rna.tf32.f32 %0, %1;" : "=r"(u) : "f"(f));
    return u;
}
__device__ __forceinline__ void mma8(float* c, unsigned a0, unsigned a1, unsigned a2,
                                     unsigned a3, unsigned b0, unsigned b1) {
    asm volatile(
        "mma.sync.aligned.m16n8k8.row.col.f32.tf32.tf32.f32 "
        "{%0,%1,%2,%3},{%4,%5,%6,%7},{%8,%9},{%0,%1,%2,%3};"
        : "+f"(c[0]), "+f"(c[1]), "+f"(c[2]), "+f"(c[3])
        : "r"(a0), "r"(a1), "r"(a2), "r"(a3), "r"(b0), "r"(b1));
}
__device__ __forceinline__ void ldsm4(unsigned& r0, unsigned& r1, unsigned& r2,
                                      unsigned& r3, unsigned a) {
    asm volatile("ldmatrix.sync.aligned.m8n8.x4.shared.b16 {%0,%1,%2,%3},[%4];"
                 : "=r"(r0), "=r"(r1), "=r"(r2), "=r"(r3) : "r"(a));
}

// ---------------------------------------------------------------------------
// K1: s_id, s_q row dot products
// ---------------------------------------------------------------------------
__global__ void scores_kernel(const float* __restrict__ Uq,
                              const float* __restrict__ Uid,
                              const float* __restrict__ Wc_w) {
    int gwarp = (blockIdx.x * blockDim.x + threadIdx.x) >> 5;
    int lane = threadIdx.x & 31;
    if (gwarp >= NB * SL) return;
    float4 a  = reinterpret_cast<const float4*>(Uid + (size_t)gwarp * ED)[lane];
    float4 w1 = reinterpret_cast<const float4*>(Wc_w)[lane];
    float4 b  = reinterpret_cast<const float4*>(Uq + (size_t)gwarp * ED)[lane];
    float4 w2 = reinterpret_cast<const float4*>(Wc_w + ED)[lane];
    float s1 = a.x * w1.x + a.y * w1.y + a.z * w1.z + a.w * w1.w;
    float s2 = b.x * w2.x + b.y * w2.y + b.z * w2.z + b.w * w2.w;
    #pragma unroll
    for (int o = 16; o > 0; o >>= 1) {
        s1 += __shfl_xor_sync(0xffffffffu, s1, o);
        s2 += __shfl_xor_sync(0xffffffffu, s2, o);
    }
    if (lane == 0) { g_sid[gwarp] = s1; g_sq[gwarp] = s2; }
}

// ---------------------------------------------------------------------------
// K2: E = exp((s_mul + s_id + s_q + b) * mask), s_mul via tf32 MMA (NT, K=128)
// A = Uid .* w_mul  [m][k] ldmatrix,  B = Uq [n][k] ldmatrix
// ---------------------------------------------------------------------------
__global__ void __launch_bounds__(NTH, 1)
e_kernel(const float* __restrict__ Uq, const float* __restrict__ Uid,
         const float* __restrict__ mask, const float* __restrict__ Wc_w,
         const float* __restrict__ Wc_b) {
    __shared__ unsigned As[2][BM][PAD_LD];
    __shared__ unsigned Bs[2][BN][PAD_LD];
    int b = blockIdx.z, i0 = blockIdx.y * BM, j0 = blockIdx.x * BN;
    const float* Ap = Uid + (size_t)b * SL * ED;
    const float* Bp = Uq + (size_t)b * SL * ED;
    const float* wm = Wc_w + 2 * ED;
    int tid = threadIdx.x, lane = tid & 31, wid = tid >> 5;
    int wm_ = wid & 3, wn_ = wid >> 2;   // 4 m-warps x 2 n-warps
    float acc[2][8][4] = {};
    float4 ra[2], rb[2], rww[2];

    auto loadT = [&](int kk) {
        #pragma unroll
        for (int p = 0; p < 2; p++) {
            int f = tid + p * NTH, r = f >> 2, c = (f & 3) * 4;
            ra[p]  = *(const float4*)(Ap + (size_t)(i0 + r) * ED + kk + c);
            rww[p] = *(const float4*)(wm + kk + c);
            rb[p]  = *(const float4*)(Bp + (size_t)(j0 + r) * ED + kk + c);
        }
    };
    auto storeT = [&](int buf) {
        #pragma unroll
        for (int p = 0; p < 2; p++) {
            int f = tid + p * NTH, r = f >> 2, c = (f & 3) * 4;
            As[buf][r][c + 0] = f2tf(ra[p].x * rww[p].x);
            As[buf][r][c + 1] = f2tf(ra[p].y * rww[p].y);
            As[buf][r][c + 2] = f2tf(ra[p].z * rww[p].z);
            As[buf][r][c + 3] = f2tf(ra[p].w * rww[p].w);
            Bs[buf][r][c + 0] = f2tf(rb[p].x);
            Bs[buf][r][c + 1] = f2tf(rb[p].y);
            Bs[buf][r][c + 2] = f2tf(rb[p].z);
            Bs[buf][r][c + 3] = f2tf(rb[p].w);
        }
    };
    auto compute = [&](int buf) {
        unsigned abase = (unsigned)__cvta_generic_to_shared(&As[buf][0][0]);
        unsigned bbase = (unsigned)__cvta_generic_to_shared(&Bs[buf][0][0]);
        #pragma unroll
        for (int kc = 0; kc < BK; kc += 8) {
            unsigned af[2][4];
            #pragma unroll
            for (int mt = 0; mt < 2; mt++) {
                int row = wm_ * 32 + mt * 16 + (lane & 7) + ((lane >> 3) & 1) * 8;
                int col = kc + (lane >> 4) * 4;
                ldsm4(af[mt][0], af[mt][1], af[mt][2], af[mt][3],
                      abase + (unsigned)(row * PAD_LD + col) * 4u);
            }
            unsigned bf[8][2];
            #pragma unroll
            for (int np = 0; np < 4; np++) {
                int row = wn_ * 64 + np * 16 + ((lane >> 4) & 1) * 8 + (lane & 7);
                int col = kc + ((lane >> 3) & 1) * 4;
                ldsm4(bf[np * 2][0], bf[np * 2][1], bf[np * 2 + 1][0], bf[np * 2 + 1][1],
                      bbase + (unsigned)(row * PAD_LD + col) * 4u);
            }
            #pragma unroll
            for (int mt = 0; mt < 2; mt++)
                #pragma unroll
                for (int nt = 0; nt < 8; nt++)
                    mma8(acc[mt][nt], af[mt][0], af[mt][1], af[mt][2], af[mt][3],
                         bf[nt][0], bf[nt][1]);
        }
    };

    constexpr int NT = ED / BK;  // 8
    loadT(0); storeT(0); __syncthreads();
    for (int t = 0; t < NT; t++) {
        int cur = t & 1;
        if (t + 1 < NT) loadT((t + 1) * BK);
        compute(cur);
        if (t + 1 < NT) { storeT(cur ^ 1); __syncthreads(); }
    }

    float bias = Wc_b[0];
    float* Eout = g_E + (size_t)b * SL * SL;
    int r0 = lane >> 2, cc = (lane & 3) * 2;
    #pragma unroll
    for (int mt = 0; mt < 2; mt++) {
        int ibase = i0 + wm_ * 32 + mt * 16;
        #pragma unroll
        for (int half = 0; half < 2; half++) {
            int i = ibase + r0 + half * 8;
            float si = g_sid[b * SL + i] + bias;
            const float* mrow = mask + (size_t)i * SL;
            float* erow = Eout + (size_t)i * SL;
            #pragma unroll
            for (int nt = 0; nt < 8; nt++) {
                int j = j0 + wn_ * 64 + nt * 8 + cc;
                float2 mk  = *(const float2*)(mrow + j);
                float2 sq2 = *(const float2*)(&g_sq[b * SL + j]);
                float e0 = __expf((acc[mt][nt][half * 2 + 0] + si + sq2.x) * mk.x);
                float e1 = __expf((acc[mt][nt][half * 2 + 1] + si + sq2.y) * mk.y);
                *(float2*)(erow + j) = make_float2(e0, e1);
            }
        }
    }
}

// ---------------------------------------------------------------------------
// K3: column sums (two-stage, deterministic)
// ---------------------------------------------------------------------------
__global__ void colsum1_kernel() {
    int b = blockIdx.z, ch = blockIdx.y;
    int j = blockIdx.x * blockDim.x + threadIdx.x;
    const float* Ep = g_E + (size_t)b * SL * SL + j;
    int i0 = ch * (SL / CCH);
    float s0 = 0.f, s1 = 0.f, s2 = 0.f, s3 = 0.f;
    for (int i = i0; i < i0 + SL / CCH; i += 4) {
        s0 += Ep[(size_t)(i + 0) * SL];
        s1 += Ep[(size_t)(i + 1) * SL];
        s2 += Ep[(size_t)(i + 2) * SL];
        s3 += Ep[(size_t)(i + 3) * SL];
    }
    g_cpart[(b * CCH + ch) * SL + j] = (s0 + s1) + (s2 + s3);
}

__global__ void colsum2_kernel() {
    int idx = blockIdx.x * blockDim.x + threadIdx.x;
    float s = 0.f;
    int b = idx / SL, j = idx % SL;
    #pragma unroll
    for (int ch = 0; ch < CCH; ch++) s += g_cpart[(b * CCH + ch) * SL + j];
    g_c[idx] = s;
}

__global__ void scale_uq_kernel(const float* __restrict__ Uq) {
    int idx = blockIdx.x * blockDim.x + threadIdx.x;
    int row = idx / (ED / 4);
    float rc = 1.0f / g_c[row];
    float4 v = reinterpret_cast<const float4*>(Uq)[idx];
    v.x *= rc; v.y *= rc; v.z *= rc; v.w *= rc;
    reinterpret_cast<float4*>(g_Uqs)[idx] = v;
}

// ---------------------------------------------------------------------------
// NN GEMM (tf32 MMA): C[i,e] = sum_j E[i,j] * X[j,e]   M=2048,N=128,K=2048
// A = E [m][k] ldmatrix; B = X staged [k][n] scalar-LDS fragments.
// MODE 0 -> g_AD2Q;  MODE 1 -> A_Q2D fused with final assembly.
// ---------------------------------------------------------------------------
template <int MODE>
__global__ void __launch_bounds__(NTH, 1)
gemm_nn_kernel(const float* __restrict__ Uid, float* __restrict__ outp) {
    __shared__ unsigned As[2][BM][PAD_LD];
    __shared__ unsigned Bs[2][BK][PAD_SC];
    int b = blockIdx.z, i0 = blockIdx.y * BM;
    const float* Ap = g_E + (size_t)b * SL * SL;
    const float* Bp = (MODE == 0 ? g_Uqs : g_Ts) + (size_t)b * SL * ED;
    int tid = threadIdx.x, lane = tid & 31, wid = tid >> 5;
    int wm_ = wid & 3, wn_ = wid >> 2;
    float acc[2][8][4] = {};
    float4 ra[2], rb[2];

    auto loadT = [&](int kk) {
        #pragma unroll
        for (int p = 0; p < 2; p++) {
            int f = tid + p * NTH;
            int rA = f >> 2, cA = (f & 3) * 4;
            ra[p] = *(const float4*)(Ap + (size_t)(i0 + rA) * SL + kk + cA);
            int rB = f >> 5, cB = (f & 31) * 4;
            rb[p] = *(const float4*)(Bp + (size_t)(kk + rB) * ED + cB);
        }
    };
    auto storeT = [&](int buf) {
        #pragma unroll
        for (int p = 0; p < 2; p++) {
            int f = tid + p * NTH;
            int rA = f >> 2, cA = (f & 3) * 4;
            As[buf][rA][cA + 0] = f2tf(ra[p].x);
            As[buf][rA][cA + 1] = f2tf(ra[p].y);
            As[buf][rA][cA + 2] = f2tf(ra[p].z);
            As[buf][rA][cA + 3] = f2tf(ra[p].w);
            int rB = f >> 5, cB = (f & 31) * 4;
            Bs[buf][rB][cB + 0] = f2tf(rb[p].x);
            Bs[buf][rB][cB + 1] = f2tf(rb[p].y);
            Bs[buf][rB][cB + 2] = f2tf(rb[p].z);
            Bs[buf][rB][cB + 3] = f2tf(rb[p].w);
        }
    };
    auto compute = [&](int buf) {
        unsigned abase = (unsigned)__cvta_generic_to_shared(&As[buf][0][0]);
        #pragma unroll
        for (int kc = 0; kc < BK; kc += 8) {
            unsigned af[2][4];
            #pragma unroll
            for (int mt = 0; mt < 2; mt++) {
                int row = wm_ * 32 + mt * 16 + (lane & 7) + ((lane >> 3) & 1) * 8;
                int col = kc + (lane >> 4) * 4;
                ldsm4(af[mt][0], af[mt][1], af[mt][2], af[mt][3],
                      abase + (unsigned)(row * PAD_LD + col) * 4u);
            }
            unsigned bf[8][2];
            #pragma unroll
            for (int nt = 0; nt < 8; nt++) {
                int n = wn_ * 64 + nt * 8 + (lane >> 2);
                bf[nt][0] = Bs[buf][kc + (lane & 3)][n];
                bf[nt][1] = Bs[buf][kc + 4 + (lane & 3)][n];
            }
            #pragma unroll
            for (int mt = 0; mt < 2; mt++)
                #pragma unroll
                for (int nt = 0; nt < 8; nt++)
                    mma8(acc[mt][nt], af[mt][0], af[mt][1], af[mt][2], af[mt][3],
                         bf[nt][0], bf[nt][1]);
        }
    };

    constexpr int NT = SL / BK;  // 128
    loadT(0); storeT(0); __syncthreads();
    for (int t = 0; t < NT; t++) {
        int cur = t & 1;
        if (t + 1 < NT) loadT((t + 1) * BK);
        compute(cur);
        if (t + 1 < NT) { storeT(cur ^ 1); __syncthreads(); }
    }

    int r0 = lane >> 2, cc = (lane & 3) * 2;
    #pragma unroll
    for (int mt = 0; mt < 2; mt++) {
        #pragma unroll
        for (int half = 0; half < 2; half++) {
            int i = i0 + wm_ * 32 + mt * 16 + r0 + half * 8;
            size_t row = (size_t)b * SL + i;
            if (MODE == 0) {
                float* orow = g_AD2Q + row * ED;
                #pragma unroll
                for (int nt = 0; nt < 8; nt++) {
                    int e = wn_ * 64 + nt * 8 + cc;
                    *(float2*)(orow + e) =
                        make_float2(acc[mt][nt][half * 2], acc[mt][nt][half * 2 + 1]);
                }
            } else {
                const float* uidr = Uid + row * ED;
                const float* adr = g_AD2Q + row * ED;
                float* orow = outp + row * (4 * ED);
                #pragma unroll
                for (int nt = 0; nt < 8; nt++) {
                    int e = wn_ * 64 + nt * 8 + cc;
                    float2 uv = *(const float2*)(uidr + e);
                    float2 ad = *(const float2*)(adr + e);
                    float aq0 = acc[mt][nt][half * 2], aq1 = acc[mt][nt][half * 2 + 1];
                    *(float2*)(orow + e) = uv;
                    *(float2*)(orow + ED + e) = ad;
                    *(float2*)(orow + 2 * ED + e) = make_float2(uv.x * ad.x, uv.y * ad.y);
                    *(float2*)(orow + 3 * ED + e) = make_float2(uv.x * aq0, uv.y * aq1);
                }
            }
        }
    }
}

// ---------------------------------------------------------------------------
// TN GEMM (tf32 MMA): Ts[j,e] = (sum_i E[i,j] * Uid[i,e]) / c[j]^2
// A = E^T: staged as [k=i][m=j] scalar-LDS; B = Uid [k][n] scalar-LDS.
// ---------------------------------------------------------------------------
__global__ void __launch_bounds__(NTH, 1)
gemm_tn_kernel(const float* __restrict__ Uid) {
    __shared__ unsigned As[2][BK][PAD_SC];
    __shared__ unsigned Bs[2][BK][PAD_SC];
    int b = blockIdx.z, j0 = blockIdx.y * BM;
    const float* Ap = g_E + (size_t)b * SL * SL;
    const float* Bp = Uid + (size_t)b * SL * ED;
    int tid = threadIdx.x, lane = tid & 31, wid = tid >> 5;
    int wm_ = wid & 3, wn_ = wid >> 2;
    float acc[2][8][4] = {};
    float4 ra[2], rb[2];

    auto loadT = [&](int kk) {
        #pragma unroll
        for (int p = 0; p < 2; p++) {
            int f = tid + p * NTH;
            int r = f >> 5, c = (f & 31) * 4;
            ra[p] = *(const float4*)(Ap + (size_t)(kk + r) * SL + j0 + c);
            rb[p] = *(const float4*)(Bp + (size_t)(kk + r) * ED + c);
        }
    };
    auto storeT = [&](int buf) {
        #pragma unroll
        for (int p = 0; p < 2; p++) {
            int f = tid + p * NTH;
            int r = f >> 5, c = (f & 31) * 4;
            As[buf][r][c + 0] = f2tf(ra[p].x);
            As[buf][r][c + 1] = f2tf(ra[p].y);
            As[buf][r][c + 2] = f2tf(ra[p].z);
            As[buf][r][c + 3] = f2tf(ra[p].w);
            Bs[buf][r][c + 0] = f2tf(rb[p].x);
            Bs[buf][r][c + 1] = f2tf(rb[p].y);
            Bs[buf][r][c + 2] = f2tf(rb[p].z);
            Bs[buf][r][c + 3] = f2tf(rb[p].w);
        }
    };
    auto compute = [&](int buf) {
        #pragma unroll
        for (int kc = 0; kc < BK; kc += 8) {
            unsigned af[2][4];
            #pragma unroll
            for (int mt = 0; mt < 2; mt++) {
                int m = wm_ * 32 + mt * 16 + (lane >> 2);
                af[mt][0] = As[buf][kc + (lane & 3)][m];
                af[mt][1] = As[buf][kc + (lane & 3)][m + 8];
                af[mt][2] = As[buf][kc + 4 + (lane & 3)][m];
                af[mt][3] = As[buf][kc + 4 + (lane & 3)][m + 8];
            }
            unsigned bf[8][2];
            #pragma unroll
            for (int nt = 0; nt < 8; nt++) {
                int n = wn_ * 64 + nt * 8 + (lane >> 2);
                bf[nt][0] = Bs[buf][kc + (lane & 3)][n];
                bf[nt][1] = Bs[buf][kc + 4 + (lane & 3)][n];
            }
            #pragma unroll
            for (int mt = 0; mt < 2; mt++)
                #pragma unroll
                for (int nt = 0; nt < 8; nt++)
                    mma8(acc[mt][nt], af[mt][0], af[mt][1], af[mt][2], af[mt][3],
                         bf[nt][0], bf[nt][1]);
        }
    };

    constexpr int NT = SL / BK;  // 128
    loadT(0); storeT(0); __syncthreads();
    for (int t = 0; t < NT; t++) {
        int cur = t & 1;
        if (t + 1 < NT) loadT((t + 1) * BK);
        compute(cur);
        if (t + 1 < NT) { storeT(cur ^ 1); __syncthreads(); }
    }

    int r0 = lane >> 2, cc = (lane & 3) * 2;
    #pragma unroll
    for (int mt = 0; mt < 2; mt++) {
        #pragma unroll
        for (int half = 0; half < 2; half++) {
            int j = j0 + wm_ * 32 + mt * 16 + r0 + half * 8;
            float cj = g_c[b * SL + j];
            float s = 1.0f / (cj * cj);
            float* orow = g_Ts + ((size_t)b * SL + j) * ED;
            #pragma unroll
            for (int nt = 0; nt < 8; nt++) {
                int e = wn_ * 64 + nt * 8 + cc;
                *(float2*)(orow + e) = make_float2(acc[mt][nt][half * 2] * s,
                                                   acc[mt][nt][half * 2 + 1] * s);
            }
        }
    }
}

// ---------------------------------------------------------------------------
extern "C" void kernel_launch(void* const* d_in, const int* in_sizes, int n_in,
                              void* d_out, int out_size) {
    const float* Uq   = (const float*)d_in[0];
    const float* Uid  = (const float*)d_in[1];
    const float* mask = (const float*)d_in[2];
    const float* Wcw  = (const float*)d_in[3];
    const float* Wcb  = (const float*)d_in[4];
    float* out = (float*)d_out;

    scores_kernel<<<NB * SL / 8, 256>>>(Uq, Uid, Wcw);
    e_kernel<<<dim3(SL / BN, SL / BM, NB), NTH>>>(Uq, Uid, mask, Wcw, Wcb);
    colsum1_kernel<<<dim3(SL / 256, CCH, NB), 256>>>();
    colsum2_kernel<<<NB * SL / 256, 256>>>();
    scale_uq_kernel<<<NB * SL * ED / 4 / 256, 256>>>(Uq);
    gemm_nn_kernel<0><<<dim3(1, SL / BM, NB), NTH>>>(Uid, out);   // A_D2Q
    gemm_tn_kernel<<<dim3(1, SL / BM, NB), NTH>>>(Uid);           // Ts
    gemm_nn_kernel<1><<<dim3(1, SL / BM, NB), NTH>>>(Uid, out);   // A_Q2D + assemble
}

// round 3
// speedup vs baseline: 3.3663x; 1.4302x over previous
#include <cuda_runtime.h>

constexpr int NB = 8, SL = 2048, ED = 128;
constexpr int BM = 128, BN = 128, BK = 16;
constexpr int NTH = 256;
constexpr int PAD_A = 20;    // [m][k] ldmatrix layout stride (floats) -> conflict-free LDSM
constexpr int PAD_B = 136;   // [k][n] scalar layout stride: 136 mod 32 == 8 -> conflict-free LDS
constexpr int NCH = 16;      // colsum chunks = SL/BM

// stage region sizes (floats)
constexpr int SA = BM * PAD_A;        // 2560
constexpr int SB = BK * PAD_B;        // 2176
constexpr int STG = SA + SB;          // 4736 (gemm kernels)
constexpr int STG_E = 2 * SA;         // 5120 (e_kernel: A + B both ldsm layout)

__device__ float g_E[(size_t)NB * SL * SL];   // exp(S), tf32-rounded, 128 MiB
__device__ float g_c[NB * SL];
__device__ float g_cpart[NB * NCH * SL];
__device__ float g_sid[NB * SL];
__device__ float g_sq[NB * SL];
__device__ float g_Uidw[NB * SL * ED];  // rna(Uid .* w_mul)
__device__ float g_Uqr[NB * SL * ED];   // rna(Uq)
__device__ float g_Uidr[NB * SL * ED];  // rna(Uid)
__device__ float g_Uqs[NB * SL * ED];   // rna(Uq / c)
__device__ float g_Ts[NB * SL * ED];    // rna((E^T Uid) / c^2)
__device__ float g_AD2Q[NB * SL * ED];  // fp32

// ---------------------------------------------------------------------------
__device__ __forceinline__ float tfr(float f) {
    unsigned u;
    asm("cvt.rna.tf32.f32 %0, %1;" : "=r"(u) : "f"(f));
    return __uint_as_float(u);
}
__device__ __forceinline__ void mma8(float* c, unsigned a0, unsigned a1, unsigned a2,
                                     unsigned a3, unsigned b0, unsigned b1) {
    asm volatile(
        "mma.sync.aligned.m16n8k8.row.col.f32.tf32.tf32.f32 "
        "{%0,%1,%2,%3},{%4,%5,%6,%7},{%8,%9},{%0,%1,%2,%3};"
        : "+f"(c[0]), "+f"(c[1]), "+f"(c[2]), "+f"(c[3])
        : "r"(a0), "r"(a1), "r"(a2), "r"(a3), "r"(b0), "r"(b1));
}
__device__ __forceinline__ void ldsm4(unsigned& r0, unsigned& r1, unsigned& r2,
                                      unsigned& r3, unsigned a) {
    asm volatile("ldmatrix.sync.aligned.m8n8.x4.shared.b16 {%0,%1,%2,%3},[%4];"
                 : "=r"(r0), "=r"(r1), "=r"(r2), "=r"(r3) : "r"(a));
}
__device__ __forceinline__ void cpa16(unsigned dst, const void* src) {
    asm volatile("cp.async.cg.shared.global [%0], [%1], 16;" :: "r"(dst), "l"(src));
}
__device__ __forceinline__ void cpcommit() { asm volatile("cp.async.commit_group;"); }
template <int N> __device__ __forceinline__ void cpwait() {
    asm volatile("cp.async.wait_group %0;" :: "n"(N));
}
__device__ __forceinline__ unsigned smaddr(const void* p) {
    return (unsigned)__cvta_generic_to_shared(p);
}

// ---------------------------------------------------------------------------
// prep: s_id, s_q dots; rna-rounded copies Uidw, Uqr, Uidr
// ---------------------------------------------------------------------------
__global__ void prep_kernel(const float* __restrict__ Uq,
                            const float* __restrict__ Uid,
                            const float* __restrict__ Wc_w) {
    int gw = (blockIdx.x * blockDim.x + threadIdx.x) >> 5;
    int lane = threadIdx.x & 31;
    if (gw >= NB * SL) return;
    float4 a  = reinterpret_cast<const float4*>(Uid + (size_t)gw * ED)[lane];
    float4 q  = reinterpret_cast<const float4*>(Uq + (size_t)gw * ED)[lane];
    float4 w1 = reinterpret_cast<const float4*>(Wc_w)[lane];
    float4 w2 = reinterpret_cast<const float4*>(Wc_w + ED)[lane];
    float4 w3 = reinterpret_cast<const float4*>(Wc_w + 2 * ED)[lane];
    float s1 = a.x * w1.x + a.y * w1.y + a.z * w1.z + a.w * w1.w;
    float s2 = q.x * w2.x + q.y * w2.y + q.z * w2.z + q.w * w2.w;
    #pragma unroll
    for (int o = 16; o > 0; o >>= 1) {
        s1 += __shfl_xor_sync(0xffffffffu, s1, o);
        s2 += __shfl_xor_sync(0xffffffffu, s2, o);
    }
    if (lane == 0) { g_sid[gw] = s1; g_sq[gw] = s2; }
    float4 o1 = make_float4(tfr(a.x * w3.x), tfr(a.y * w3.y), tfr(a.z * w3.z), tfr(a.w * w3.w));
    float4 o2 = make_float4(tfr(q.x), tfr(q.y), tfr(q.z), tfr(q.w));
    float4 o3 = make_float4(tfr(a.x), tfr(a.y), tfr(a.z), tfr(a.w));
    reinterpret_cast<float4*>(g_Uidw + (size_t)gw * ED)[lane] = o1;
    reinterpret_cast<float4*>(g_Uqr  + (size_t)gw * ED)[lane] = o2;
    reinterpret_cast<float4*>(g_Uidr + (size_t)gw * ED)[lane] = o3;
}

// ---------------------------------------------------------------------------
// e_kernel: E = rna(exp((s_mul + s_id + s_q + b)*mask)); fused column partials
// A = g_Uidw [m][k], B = g_Uqr [n][k]; 3-stage cp.async; ldsm fragments
// smem: 3*STG_E + 8*BN floats = 65536 B
// ---------------------------------------------------------------------------
__global__ void __launch_bounds__(NTH)
e_kernel(const float* __restrict__ mask, const float* __restrict__ Wc_b) {
    extern __shared__ float sm[];
    int b = blockIdx.z, i0 = blockIdx.y * BM, j0 = blockIdx.x * BN;
    const float* Ap = g_Uidw + (size_t)b * SL * ED;
    const float* Bp = g_Uqr + (size_t)b * SL * ED;
    int tid = threadIdx.x, lane = tid & 31, wid = tid >> 5;
    int wm_ = wid & 3, wn_ = wid >> 2;
    float acc[2][8][4] = {};

    auto stage = [&](int s, int kk) {
        float* As = sm + s * STG_E;
        float* Bs = As + SA;
        unsigned ab = smaddr(As), bb = smaddr(Bs);
        #pragma unroll
        for (int p = 0; p < 2; p++) {
            int idx = tid + p * NTH;
            int r = idx >> 2, c = (idx & 3) * 4;
            cpa16(ab + (unsigned)(r * PAD_A + c) * 4u, Ap + (size_t)(i0 + r) * ED + kk + c);
            cpa16(bb + (unsigned)(r * PAD_A + c) * 4u, Bp + (size_t)(j0 + r) * ED + kk + c);
        }
    };
    auto compute = [&](int s) {
        float* As = sm + s * STG_E;
        float* Bs = As + SA;
        unsigned abase = smaddr(As), bbase = smaddr(Bs);
        #pragma unroll
        for (int kc = 0; kc < BK; kc += 8) {
            unsigned af[2][4];
            #pragma unroll
            for (int mt = 0; mt < 2; mt++) {
                int row = wm_ * 32 + mt * 16 + (lane & 7) + ((lane >> 3) & 1) * 8;
                int col = kc + (lane >> 4) * 4;
                ldsm4(af[mt][0], af[mt][1], af[mt][2], af[mt][3],
                      abase + (unsigned)(row * PAD_A + col) * 4u);
            }
            unsigned bf[8][2];
            #pragma unroll
            for (int np = 0; np < 4; np++) {
                int row = wn_ * 64 + np * 16 + ((lane >> 4) & 1) * 8 + (lane & 7);
                int col = kc + ((lane >> 3) & 1) * 4;
                ldsm4(bf[np * 2][0], bf[np * 2][1], bf[np * 2 + 1][0], bf[np * 2 + 1][1],
                      bbase + (unsigned)(row * PAD_A + col) * 4u);
            }
            #pragma unroll
            for (int mt = 0; mt < 2; mt++)
                #pragma unroll
                for (int nt = 0; nt < 8; nt++)
                    mma8(acc[mt][nt], af[mt][0], af[mt][1], af[mt][2], af[mt][3],
                         bf[nt][0], bf[nt][1]);
        }
    };

    constexpr int NT = ED / BK;  // 8
    stage(0, 0); cpcommit();
    stage(1, BK); cpcommit();
    for (int t = 0; t < NT; t++) {
        cpwait<1>();
        __syncthreads();
        compute(t % 3);
        if (t + 2 < NT) stage((t + 2) % 3, (t + 2) * BK);
        cpcommit();
    }

    // epilogue: exp + store + column partial sums
    float bias = Wc_b[0];
    float* Eout = g_E + (size_t)b * SL * SL;
    int r0 = lane >> 2, cc = (lane & 3) * 2;
    float csum[8][2];
    #pragma unroll
    for (int nt = 0; nt < 8; nt++) { csum[nt][0] = 0.f; csum[nt][1] = 0.f; }
    #pragma unroll
    for (int mt = 0; mt < 2; mt++) {
        #pragma unroll
        for (int half = 0; half < 2; half++) {
            int i = i0 + wm_ * 32 + mt * 16 + r0 + half * 8;
            float si = g_sid[b * SL + i] + bias;
            const float* mrow = mask + (size_t)i * SL;
            float* erow = Eout + (size_t)i * SL;
            #pragma unroll
            for (int nt = 0; nt < 8; nt++) {
                int j = j0 + wn_ * 64 + nt * 8 + cc;
                float2 mk = *(const float2*)(mrow + j);
                float2 sq2 = *(const float2*)(&g_sq[b * SL + j]);
                float e0 = tfr(__expf((acc[mt][nt][half * 2 + 0] + si + sq2.x) * mk.x));
                float e1 = tfr(__expf((acc[mt][nt][half * 2 + 1] + si + sq2.y) * mk.y));
                *(float2*)(erow + j) = make_float2(e0, e1);
                csum[nt][0] += e0;
                csum[nt][1] += e1;
            }
        }
    }
    // reduce over the 8 lane-rows (lanes sharing lane&3)
    #pragma unroll
    for (int nt = 0; nt < 8; nt++) {
        #pragma unroll
        for (int d = 0; d < 2; d++) {
            float v = csum[nt][d];
            v += __shfl_xor_sync(0xffffffffu, v, 4);
            v += __shfl_xor_sync(0xffffffffu, v, 8);
            v += __shfl_xor_sync(0xffffffffu, v, 16);
            csum[nt][d] = v;
        }
    }
    float* red = sm + 3 * STG_E;  // 8*BN floats
    if (lane < 4) {
        #pragma unroll
        for (int nt = 0; nt < 8; nt++) {
            red[wid * BN + wn_ * 64 + nt * 8 + lane * 2 + 0] = csum[nt][0];
            red[wid * BN + wn_ * 64 + nt * 8 + lane * 2 + 1] = csum[nt][1];
        }
    }
    __syncthreads();
    if (tid < BN) {
        int g = (tid >> 6) * 4;  // warps with matching wn_
        float s = red[(g + 0) * BN + tid] + red[(g + 1) * BN + tid] +
                  red[(g + 2) * BN + tid] + red[(g + 3) * BN + tid];
        g_cpart[((size_t)b * NCH + blockIdx.y) * SL + j0 + tid] = s;
    }
}

// ---------------------------------------------------------------------------
__global__ void colsum2_kernel() {
    int idx = blockIdx.x * blockDim.x + threadIdx.x;  // (b, j)
    int b = idx / SL, j = idx % SL;
    float s = 0.f;
    #pragma unroll
    for (int ch = 0; ch < NCH; ch++) s += g_cpart[((size_t)b * NCH + ch) * SL + j];
    g_c[idx] = s;
}

__global__ void scale_uq_kernel(const float* __restrict__ Uq) {
    int idx = blockIdx.x * blockDim.x + threadIdx.x;
    int row = idx / (ED / 4);
    float rc = 1.0f / g_c[row];
    float4 v = reinterpret_cast<const float4*>(Uq)[idx];
    v = make_float4(tfr(v.x * rc), tfr(v.y * rc), tfr(v.z * rc), tfr(v.w * rc));
    reinterpret_cast<float4*>(g_Uqs)[idx] = v;
}

// ---------------------------------------------------------------------------
// NN body: C[i,e] = sum_j E[i,j]*X[j,e]; A ldsm [m][k]; B scalar [k][n]
// MODE 0 -> g_AD2Q; MODE 1 -> final assembly into out
// ---------------------------------------------------------------------------
template <int MODE>
__device__ __forceinline__ void nn_body(float* sm, int b, int i0,
                                        const float* __restrict__ Uid,
                                        float* __restrict__ outp) {
    const float* Ap = g_E + (size_t)b * SL * SL;
    const float* Bp = (MODE == 0 ? g_Uqs : g_Ts) + (size_t)b * SL * ED;
    int tid = threadIdx.x, lane = tid & 31, wid = tid >> 5;
    int wm_ = wid & 3, wn_ = wid >> 2;
    float acc[2][8][4] = {};

    auto stage = [&](int s, int kk) {
        float* As = sm + s * STG;
        float* Bs = As + SA;
        unsigned ab = smaddr(As), bb = smaddr(Bs);
        #pragma unroll
        for (int p = 0; p < 2; p++) {
            int idx = tid + p * NTH;
            int rA = idx >> 2, cA = (idx & 3) * 4;
            cpa16(ab + (unsigned)(rA * PAD_A + cA) * 4u, Ap + (size_t)(i0 + rA) * SL + kk + cA);
            int rB = idx >> 5, cB = (idx & 31) * 4;
            cpa16(bb + (unsigned)(rB * PAD_B + cB) * 4u, Bp + (size_t)(kk + rB) * ED + cB);
        }
    };
    auto compute = [&](int s) {
        float* As = sm + s * STG;
        const unsigned* Bsu = (const unsigned*)(As + SA);
        unsigned abase = smaddr(As);
        #pragma unroll
        for (int kc = 0; kc < BK; kc += 8) {
            unsigned af[2][4];
            #pragma unroll
            for (int mt = 0; mt < 2; mt++) {
                int row = wm_ * 32 + mt * 16 + (lane & 7) + ((lane >> 3) & 1) * 8;
                int col = kc + (lane >> 4) * 4;
                ldsm4(af[mt][0], af[mt][1], af[mt][2], af[mt][3],
                      abase + (unsigned)(row * PAD_A + col) * 4u);
            }
            unsigned bf[8][2];
            #pragma unroll
            for (int nt = 0; nt < 8; nt++) {
                int n = wn_ * 64 + nt * 8 + (lane >> 2);
                bf[nt][0] = Bsu[(kc + (lane & 3)) * PAD_B + n];
                bf[nt][1] = Bsu[(kc + 4 + (lane & 3)) * PAD_B + n];
            }
            #pragma unroll
            for (int mt = 0; mt < 2; mt++)
                #pragma unroll
                for (int nt = 0; nt < 8; nt++)
                    mma8(acc[mt][nt], af[mt][0], af[mt][1], af[mt][2], af[mt][3],
                         bf[nt][0], bf[nt][1]);
        }
    };

    constexpr int NT = SL / BK;  // 128
    stage(0, 0); cpcommit();
    stage(1, BK); cpcommit();
    for (int t = 0; t < NT; t++) {
        cpwait<1>();
        __syncthreads();
        compute(t % 3);
        if (t + 2 < NT) stage((t + 2) % 3, (t + 2) * BK);
        cpcommit();
    }

    int r0 = lane >> 2, cc = (lane & 3) * 2;
    #pragma unroll
    for (int mt = 0; mt < 2; mt++) {
        #pragma unroll
        for (int half = 0; half < 2; half++) {
            int i = i0 + wm_ * 32 + mt * 16 + r0 + half * 8;
            size_t row = (size_t)b * SL + i;
            if (MODE == 0) {
                float* orow = g_AD2Q + row * ED;
                #pragma unroll
                for (int nt = 0; nt < 8; nt++) {
                    int e = wn_ * 64 + nt * 8 + cc;
                    *(float2*)(orow + e) =
                        make_float2(acc[mt][nt][half * 2], acc[mt][nt][half * 2 + 1]);
                }
            } else {
                const float* uidr = Uid + row * ED;
                const float* adr = g_AD2Q + row * ED;
                float* orow = outp + row * (4 * ED);
                #pragma unroll
                for (int nt = 0; nt < 8; nt++) {
                    int e = wn_ * 64 + nt * 8 + cc;
                    float2 uv = *(const float2*)(uidr + e);
                    float2 ad = *(const float2*)(adr + e);
                    float aq0 = acc[mt][nt][half * 2], aq1 = acc[mt][nt][half * 2 + 1];
                    *(float2*)(orow + e) = uv;
                    *(float2*)(orow + ED + e) = ad;
                    *(float2*)(orow + 2 * ED + e) = make_float2(uv.x * ad.x, uv.y * ad.y);
                    *(float2*)(orow + 3 * ED + e) = make_float2(uv.x * aq0, uv.y * aq1);
                }
            }
        }
    }
}

// ---------------------------------------------------------------------------
// TN body: Ts[j,e] = (sum_i E[i,j]*Uid[i,e]) / c[j]^2; both operands [k][*]
// ---------------------------------------------------------------------------
__device__ __forceinline__ void tn_body(float* sm, int b, int j0) {
    const float* Ap = g_E + (size_t)b * SL * SL;
    const float* Bp = g_Uidr + (size_t)b * SL * ED;
    int tid = threadIdx.x, lane = tid & 31, wid = tid >> 5;
    int wm_ = wid & 3, wn_ = wid >> 2;
    float acc[2][8][4] = {};

    auto stage = [&](int s, int kk) {
        float* As = sm + s * STG;
        float* Bs = As + SA;
        unsigned ab = smaddr(As), bb = smaddr(Bs);
        #pragma unroll
        for (int p = 0; p < 2; p++) {
            int idx = tid + p * NTH;
            int r = idx >> 5, c = (idx & 31) * 4;
            cpa16(ab + (unsigned)(r * PAD_B + c) * 4u, Ap + (size_t)(kk + r) * SL + j0 + c);
            cpa16(bb + (unsigned)(r * PAD_B + c) * 4u, Bp + (size_t)(kk + r) * ED + c);
        }
    };
    auto compute = [&](int s) {
        const unsigned* Asu = (const unsigned*)(sm + s * STG);
        const unsigned* Bsu = (const unsigned*)(sm + s * STG + SA);
        #pragma unroll
        for (int kc = 0; kc < BK; kc += 8) {
            unsigned af[2][4];
            #pragma unroll
            for (int mt = 0; mt < 2; mt++) {
                int m = wm_ * 32 + mt * 16 + (lane >> 2);
                af[mt][0] = Asu[(kc + (lane & 3)) * PAD_B + m];
                af[mt][1] = Asu[(kc + (lane & 3)) * PAD_B + m + 8];
                af[mt][2] = Asu[(kc + 4 + (lane & 3)) * PAD_B + m];
                af[mt][3] = Asu[(kc + 4 + (lane & 3)) * PAD_B + m + 8];
            }
            unsigned bf[8][2];
            #pragma unroll
            for (int nt = 0; nt < 8; nt++) {
                int n = wn_ * 64 + nt * 8 + (lane >> 2);
                bf[nt][0] = Bsu[(kc + (lane & 3)) * PAD_B + n];
                bf[nt][1] = Bsu[(kc + 4 + (lane & 3)) * PAD_B + n];
            }
            #pragma unroll
            for (int mt = 0; mt < 2; mt++)
                #pragma unroll
                for (int nt = 0; nt < 8; nt++)
                    mma8(acc[mt][nt], af[mt][0], af[mt][1], af[mt][2], af[mt][3],
                         bf[nt][0], bf[nt][1]);
        }
    };

    constexpr int NT = SL / BK;
    stage(0, 0); cpcommit();
    stage(1, BK); cpcommit();
    for (int t = 0; t < NT; t++) {
        cpwait<1>();
        __syncthreads();
        compute(t % 3);
        if (t + 2 < NT) stage((t + 2) % 3, (t + 2) * BK);
        cpcommit();
    }

    int r0 = lane >> 2, cc = (lane & 3) * 2;
    #pragma unroll
    for (int mt = 0; mt < 2; mt++) {
        #pragma unroll
        for (int half = 0; half < 2; half++) {
            int j = j0 + wm_ * 32 + mt * 16 + r0 + half * 8;
            float cj = g_c[b * SL + j];
            float s = 1.0f / (cj * cj);
            float* orow = g_Ts + ((size_t)b * SL + j) * ED;
            #pragma unroll
            for (int nt = 0; nt < 8; nt++) {
                int e = wn_ * 64 + nt * 8 + cc;
                *(float2*)(orow + e) = make_float2(tfr(acc[mt][nt][half * 2] * s),
                                                   tfr(acc[mt][nt][half * 2 + 1] * s));
            }
        }
    }
}

// fused NN0 + TN kernel: blockIdx.y < NCH -> NN0 tile, else TN tile
__global__ void __launch_bounds__(NTH)
gemm2_kernel() {
    extern __shared__ float sm[];
    int b = blockIdx.z;
    int t0 = (blockIdx.y & 15) * BM;
    if (blockIdx.y < NCH) nn_body<0>(sm, b, t0, nullptr, nullptr);
    else                  tn_body(sm, b, t0);
}

__global__ void __launch_bounds__(NTH)
nn1_kernel(const float* __restrict__ Uid, float* __restrict__ outp) {
    extern __shared__ float sm[];
    nn_body<1>(sm, blockIdx.z, blockIdx.y * BM, Uid, outp);
}

// ---------------------------------------------------------------------------
extern "C" void kernel_launch(void* const* d_in, const int* in_sizes, int n_in,
                              void* d_out, int out_size) {
    const float* Uq   = (const float*)d_in[0];
    const float* Uid  = (const float*)d_in[1];
    const float* mask = (const float*)d_in[2];
    const float* Wcw  = (const float*)d_in[3];
    const float* Wcb  = (const float*)d_in[4];
    float* out = (float*)d_out;

    constexpr int SM_E = (3 * STG_E + 8 * BN) * 4;  // 65536
    constexpr int SM_G = 3 * STG * 4;               // 56832
    cudaFuncSetAttribute(e_kernel, cudaFuncAttributeMaxDynamicSharedMemorySize, SM_E);
    cudaFuncSetAttribute(gemm2_kernel, cudaFuncAttributeMaxDynamicSharedMemorySize, SM_G);
    cudaFuncSetAttribute(nn1_kernel, cudaFuncAttributeMaxDynamicSharedMemorySize, SM_G);

    prep_kernel<<<NB * SL / 8, 256>>>(Uq, Uid, Wcw);
    e_kernel<<<dim3(SL / BN, SL / BM, NB), NTH, SM_E>>>(mask, Wcb);
    colsum2_kernel<<<NB * SL / 256, 256>>>();
    scale_uq_kernel<<<NB * SL * ED / 4 / 256, 256>>>(Uq);
    gemm2_kernel<<<dim3(1, 2 * NCH, NB), NTH, SM_G>>>();
    nn1_kernel<<<dim3(1, NCH, NB), NTH, SM_G>>>(Uid, out);
}

// round 4
// speedup vs baseline: 3.5394x; 1.0514x over previous
#include <cuda_runtime.h>

constexpr int NB = 8, SL = 2048, ED = 128;
constexpr int BM = 128, BN = 128, BK = 16;
constexpr int NTH = 256;
constexpr int PAD_A = 20;    // [m][k] ldmatrix layout stride -> conflict-free LDSM
constexpr int PAD_B = 136;   // [k][n] scalar layout stride (136 mod 32 == 8) -> conflict-free LDS
constexpr int NCH = 16;      // SL/BM

constexpr int SA = BM * PAD_A;          // 2560 floats
constexpr int SB = BK * PAD_B;          // 2176 floats
constexpr int STG_T = SA + SB;          // tn kernel stage
constexpr int STG_E = 2 * SA;           // e_kernel stage
constexpr int STG_F = SA + 2 * SB;      // fused nn stage (A + two B tiles)

__device__ float g_E[(size_t)NB * SL * SL];
__device__ float g_c[NB * SL];
__device__ float g_cpart[NB * NCH * SL];
__device__ float g_sid[NB * SL];
__device__ float g_sq[NB * SL];
__device__ float g_Uidw[NB * SL * ED];  // rna(Uid .* w_mul)
__device__ float g_Uqr[NB * SL * ED];   // rna(Uq)
__device__ float g_Uidr[NB * SL * ED];  // rna(Uid)
__device__ float g_Uqs[NB * SL * ED];   // rna(Uq / c)
__device__ float g_Ts[NB * SL * ED];    // rna((E^T Uid) / c^2)

// ---------------------------------------------------------------------------
__device__ __forceinline__ float tfr(float f) {
    unsigned u;
    asm("cvt.rna.tf32.f32 %0, %1;" : "=r"(u) : "f"(f));
    return __uint_as_float(u);
}
__device__ __forceinline__ void mma8(float* c, unsigned a0, unsigned a1, unsigned a2,
                                     unsigned a3, unsigned b0, unsigned b1) {
    asm volatile(
        "mma.sync.aligned.m16n8k8.row.col.f32.tf32.tf32.f32 "
        "{%0,%1,%2,%3},{%4,%5,%6,%7},{%8,%9},{%0,%1,%2,%3};"
        : "+f"(c[0]), "+f"(c[1]), "+f"(c[2]), "+f"(c[3])
        : "r"(a0), "r"(a1), "r"(a2), "r"(a3), "r"(b0), "r"(b1));
}
__device__ __forceinline__ void ldsm4(unsigned& r0, unsigned& r1, unsigned& r2,
                                      unsigned& r3, unsigned a) {
    asm volatile("ldmatrix.sync.aligned.m8n8.x4.shared.b16 {%0,%1,%2,%3},[%4];"
                 : "=r"(r0), "=r"(r1), "=r"(r2), "=r"(r3) : "r"(a));
}
__device__ __forceinline__ void cpa16(unsigned dst, const void* src) {
    asm volatile("cp.async.cg.shared.global [%0], [%1], 16;" :: "r"(dst), "l"(src));
}
__device__ __forceinline__ void cpcommit() { asm volatile("cp.async.commit_group;"); }
template <int N> __device__ __forceinline__ void cpwait() {
    asm volatile("cp.async.wait_group %0;" :: "n"(N));
}
__device__ __forceinline__ unsigned smaddr(const void* p) {
    return (unsigned)__cvta_generic_to_shared(p);
}

// ---------------------------------------------------------------------------
// prep: s_id, s_q dots; rna-rounded operand copies
// ---------------------------------------------------------------------------
__global__ void prep_kernel(const float* __restrict__ Uq,
                            const float* __restrict__ Uid,
                            const float* __restrict__ Wc_w) {
    int gw = (blockIdx.x * blockDim.x + threadIdx.x) >> 5;
    int lane = threadIdx.x & 31;
    if (gw >= NB * SL) return;
    float4 a  = reinterpret_cast<const float4*>(Uid + (size_t)gw * ED)[lane];
    float4 q  = reinterpret_cast<const float4*>(Uq + (size_t)gw * ED)[lane];
    float4 w1 = reinterpret_cast<const float4*>(Wc_w)[lane];
    float4 w2 = reinterpret_cast<const float4*>(Wc_w + ED)[lane];
    float4 w3 = reinterpret_cast<const float4*>(Wc_w + 2 * ED)[lane];
    float s1 = a.x * w1.x + a.y * w1.y + a.z * w1.z + a.w * w1.w;
    float s2 = q.x * w2.x + q.y * w2.y + q.z * w2.z + q.w * w2.w;
    #pragma unroll
    for (int o = 16; o > 0; o >>= 1) {
        s1 += __shfl_xor_sync(0xffffffffu, s1, o);
        s2 += __shfl_xor_sync(0xffffffffu, s2, o);
    }
    if (lane == 0) { g_sid[gw] = s1; g_sq[gw] = s2; }
    float4 o1 = make_float4(tfr(a.x * w3.x), tfr(a.y * w3.y), tfr(a.z * w3.z), tfr(a.w * w3.w));
    float4 o2 = make_float4(tfr(q.x), tfr(q.y), tfr(q.z), tfr(q.w));
    float4 o3 = make_float4(tfr(a.x), tfr(a.y), tfr(a.z), tfr(a.w));
    reinterpret_cast<float4*>(g_Uidw + (size_t)gw * ED)[lane] = o1;
    reinterpret_cast<float4*>(g_Uqr  + (size_t)gw * ED)[lane] = o2;
    reinterpret_cast<float4*>(g_Uidr + (size_t)gw * ED)[lane] = o3;
}

// ---------------------------------------------------------------------------
// e_kernel: E = rna(exp((s_mul+s_id+s_q+b)*mask)); fused column partial sums
// grid (b fastest, j, i) -> 8 consecutive blocks share one mask tile in L2
// ---------------------------------------------------------------------------
__global__ void __launch_bounds__(NTH)
e_kernel(const float* __restrict__ mask, const float* __restrict__ Wc_b) {
    extern __shared__ float sm[];
    int b = blockIdx.x, j0 = blockIdx.y * BN, i0 = blockIdx.z * BM;
    const float* Ap = g_Uidw + (size_t)b * SL * ED;
    const float* Bp = g_Uqr + (size_t)b * SL * ED;
    int tid = threadIdx.x, lane = tid & 31, wid = tid >> 5;
    int wm_ = wid & 3, wn_ = wid >> 2;
    float acc[2][8][4] = {};

    auto stage = [&](int s, int kk) {
        float* As = sm + s * STG_E;
        float* Bs = As + SA;
        unsigned ab = smaddr(As), bb = smaddr(Bs);
        #pragma unroll
        for (int p = 0; p < 2; p++) {
            int idx = tid + p * NTH;
            int r = idx >> 2, c = (idx & 3) * 4;
            cpa16(ab + (unsigned)(r * PAD_A + c) * 4u, Ap + (size_t)(i0 + r) * ED + kk + c);
            cpa16(bb + (unsigned)(r * PAD_A + c) * 4u, Bp + (size_t)(j0 + r) * ED + kk + c);
        }
    };
    auto compute = [&](int s) {
        float* As = sm + s * STG_E;
        float* Bs = As + SA;
        unsigned abase = smaddr(As), bbase = smaddr(Bs);
        #pragma unroll
        for (int kc = 0; kc < BK; kc += 8) {
            unsigned af[2][4];
            #pragma unroll
            for (int mt = 0; mt < 2; mt++) {
                int row = wm_ * 32 + mt * 16 + (lane & 7) + ((lane >> 3) & 1) * 8;
                int col = kc + (lane >> 4) * 4;
                ldsm4(af[mt][0], af[mt][1], af[mt][2], af[mt][3],
                      abase + (unsigned)(row * PAD_A + col) * 4u);
            }
            unsigned bf[8][2];
            #pragma unroll
            for (int np = 0; np < 4; np++) {
                int row = wn_ * 64 + np * 16 + ((lane >> 4) & 1) * 8 + (lane & 7);
                int col = kc + ((lane >> 3) & 1) * 4;
                ldsm4(bf[np * 2][0], bf[np * 2][1], bf[np * 2 + 1][0], bf[np * 2 + 1][1],
                      bbase + (unsigned)(row * PAD_A + col) * 4u);
            }
            #pragma unroll
            for (int mt = 0; mt < 2; mt++)
                #pragma unroll
                for (int nt = 0; nt < 8; nt++)
                    mma8(acc[mt][nt], af[mt][0], af[mt][1], af[mt][2], af[mt][3],
                         bf[nt][0], bf[nt][1]);
        }
    };

    constexpr int NT = ED / BK;  // 8
    stage(0, 0); cpcommit();
    stage(1, BK); cpcommit();
    for (int t = 0; t < NT; t++) {
        cpwait<1>();
        __syncthreads();
        compute(t % 3);
        if (t + 2 < NT) stage((t + 2) % 3, (t + 2) * BK);
        cpcommit();
    }

    float bias = Wc_b[0];
    float* Eout = g_E + (size_t)b * SL * SL;
    int r0 = lane >> 2, cc = (lane & 3) * 2;
    float csum[8][2];
    #pragma unroll
    for (int nt = 0; nt < 8; nt++) { csum[nt][0] = 0.f; csum[nt][1] = 0.f; }
    #pragma unroll
    for (int mt = 0; mt < 2; mt++) {
        #pragma unroll
        for (int half = 0; half < 2; half++) {
            int i = i0 + wm_ * 32 + mt * 16 + r0 + half * 8;
            float si = g_sid[b * SL + i] + bias;
            const float* mrow = mask + (size_t)i * SL;
            float* erow = Eout + (size_t)i * SL;
            #pragma unroll
            for (int nt = 0; nt < 8; nt++) {
                int j = j0 + wn_ * 64 + nt * 8 + cc;
                float2 mk = __ldg((const float2*)(mrow + j));
                float2 sq2 = *(const float2*)(&g_sq[b * SL + j]);
                float e0 = tfr(__expf((acc[mt][nt][half * 2 + 0] + si + sq2.x) * mk.x));
                float e1 = tfr(__expf((acc[mt][nt][half * 2 + 1] + si + sq2.y) * mk.y));
                __stcs((float2*)(erow + j), make_float2(e0, e1));
                csum[nt][0] += e0;
                csum[nt][1] += e1;
            }
        }
    }
    #pragma unroll
    for (int nt = 0; nt < 8; nt++) {
        #pragma unroll
        for (int d = 0; d < 2; d++) {
            float v = csum[nt][d];
            v += __shfl_xor_sync(0xffffffffu, v, 4);
            v += __shfl_xor_sync(0xffffffffu, v, 8);
            v += __shfl_xor_sync(0xffffffffu, v, 16);
            csum[nt][d] = v;
        }
    }
    float* red = sm + 3 * STG_E;
    if (lane < 4) {
        #pragma unroll
        for (int nt = 0; nt < 8; nt++) {
            red[wid * BN + wn_ * 64 + nt * 8 + lane * 2 + 0] = csum[nt][0];
            red[wid * BN + wn_ * 64 + nt * 8 + lane * 2 + 1] = csum[nt][1];
        }
    }
    __syncthreads();
    if (tid < BN) {
        int g = (tid >> 6) * 4;
        float s = red[(g + 0) * BN + tid] + red[(g + 1) * BN + tid] +
                  red[(g + 2) * BN + tid] + red[(g + 3) * BN + tid];
        g_cpart[((size_t)b * NCH + blockIdx.z) * SL + j0 + tid] = s;
    }
}

// ---------------------------------------------------------------------------
// colsum finish + Uqs = rna(Uq / c): one block = 256 (b,j) rows
// ---------------------------------------------------------------------------
__global__ void __launch_bounds__(256)
colsum_scale_kernel(const float* __restrict__ Uq) {
    __shared__ float rcs[256];
    int tid = threadIdx.x;
    int base = blockIdx.x * 256;
    int idx = base + tid;
    int b = idx / SL, j = idx % SL;
    float s = 0.f;
    #pragma unroll
    for (int ch = 0; ch < NCH; ch++) s += g_cpart[((size_t)b * NCH + ch) * SL + j];
    g_c[idx] = s;
    rcs[tid] = 1.0f / s;
    __syncthreads();
    #pragma unroll
    for (int it = 0; it < 32; it++) {
        int flat = it * 256 + tid;           // float4 slot within the block's 256 rows
        int rl = flat >> 5, e4 = flat & 31;
        int row = base + rl;
        float rc = rcs[rl];
        float4 v = reinterpret_cast<const float4*>(Uq + (size_t)row * ED)[e4];
        v = make_float4(tfr(v.x * rc), tfr(v.y * rc), tfr(v.z * rc), tfr(v.w * rc));
        reinterpret_cast<float4*>(g_Uqs + (size_t)row * ED)[e4] = v;
    }
}

// ---------------------------------------------------------------------------
// TN: Ts[j,e] = rna((sum_i E[i,j]*Uid[i,e]) / c[j]^2)
// ---------------------------------------------------------------------------
__global__ void __launch_bounds__(NTH)
tn_kernel() {
    extern __shared__ float sm[];
    int b = blockIdx.z, j0 = blockIdx.y * BM;
    const float* Ap = g_E + (size_t)b * SL * SL;
    const float* Bp = g_Uidr + (size_t)b * SL * ED;
    int tid = threadIdx.x, lane = tid & 31, wid = tid >> 5;
    int wm_ = wid & 3, wn_ = wid >> 2;
    float acc[2][8][4] = {};

    auto stage = [&](int s, int kk) {
        float* As = sm + s * STG_T;
        float* Bs = As + SB;  // A region is [k][m] = SB floats here
        unsigned ab = smaddr(As), bb = smaddr(Bs);
        #pragma unroll
        for (int p = 0; p < 2; p++) {
            int idx = tid + p * NTH;
            int r = idx >> 5, c = (idx & 31) * 4;
            cpa16(ab + (unsigned)(r * PAD_B + c) * 4u, Ap + (size_t)(kk + r) * SL + j0 + c);
            cpa16(bb + (unsigned)(r * PAD_B + c) * 4u, Bp + (size_t)(kk + r) * ED + c);
        }
    };
    auto compute = [&](int s) {
        const unsigned* Asu = (const unsigned*)(sm + s * STG_T);
        const unsigned* Bsu = (const unsigned*)(sm + s * STG_T + SB);
        #pragma unroll
        for (int kc = 0; kc < BK; kc += 8) {
            unsigned af[2][4];
            #pragma unroll
            for (int mt = 0; mt < 2; mt++) {
                int m = wm_ * 32 + mt * 16 + (lane >> 2);
                af[mt][0] = Asu[(kc + (lane & 3)) * PAD_B + m];
                af[mt][1] = Asu[(kc + (lane & 3)) * PAD_B + m + 8];
                af[mt][2] = Asu[(kc + 4 + (lane & 3)) * PAD_B + m];
                af[mt][3] = Asu[(kc + 4 + (lane & 3)) * PAD_B + m + 8];
            }
            unsigned bf[8][2];
            #pragma unroll
            for (int nt = 0; nt < 8; nt++) {
                int n = wn_ * 64 + nt * 8 + (lane >> 2);
                bf[nt][0] = Bsu[(kc + (lane & 3)) * PAD_B + n];
                bf[nt][1] = Bsu[(kc + 4 + (lane & 3)) * PAD_B + n];
            }
            #pragma unroll
            for (int mt = 0; mt < 2; mt++)
                #pragma unroll
                for (int nt = 0; nt < 8; nt++)
                    mma8(acc[mt][nt], af[mt][0], af[mt][1], af[mt][2], af[mt][3],
                         bf[nt][0], bf[nt][1]);
        }
    };

    constexpr int NT = SL / BK;
    stage(0, 0); cpcommit();
    stage(1, BK); cpcommit();
    for (int t = 0; t < NT; t++) {
        cpwait<1>();
        __syncthreads();
        compute(t % 3);
        if (t + 2 < NT) stage((t + 2) % 3, (t + 2) * BK);
        cpcommit();
    }

    int r0 = lane >> 2, cc = (lane & 3) * 2;
    #pragma unroll
    for (int mt = 0; mt < 2; mt++) {
        #pragma unroll
        for (int half = 0; half < 2; half++) {
            int j = j0 + wm_ * 32 + mt * 16 + r0 + half * 8;
            float cj = g_c[b * SL + j];
            float s = 1.0f / (cj * cj);
            float* orow = g_Ts + ((size_t)b * SL + j) * ED;
            #pragma unroll
            for (int nt = 0; nt < 8; nt++) {
                int e = wn_ * 64 + nt * 8 + cc;
                *(float2*)(orow + e) = make_float2(tfr(acc[mt][nt][half * 2] * s),
                                                   tfr(acc[mt][nt][half * 2 + 1] * s));
            }
        }
    }
}

// ---------------------------------------------------------------------------
// Fused NN: one E pass computes A_D2Q = E@Uqs AND A_Q2D = E@Ts, then writes
// the fully assembled output. A_D2Q never hits DRAM.
// ---------------------------------------------------------------------------
__global__ void __launch_bounds__(NTH)
nnf_kernel(const float* __restrict__ Uid, float* __restrict__ outp) {
    extern __shared__ float sm[];
    int b = blockIdx.z, i0 = blockIdx.y * BM;
    const float* Ap = g_E + (size_t)b * SL * SL;
    const float* B0p = g_Uqs + (size_t)b * SL * ED;
    const float* B1p = g_Ts + (size_t)b * SL * ED;
    int tid = threadIdx.x, lane = tid & 31, wid = tid >> 5;
    int wm_ = wid & 3, wn_ = wid >> 2;
    float acc0[2][8][4] = {};
    float acc1[2][8][4] = {};

    auto stage = [&](int s, int kk) {
        float* As = sm + s * STG_F;
        float* Bs0 = As + SA;
        float* Bs1 = Bs0 + SB;
        unsigned ab = smaddr(As), b0 = smaddr(Bs0), b1 = smaddr(Bs1);
        #pragma unroll
        for (int p = 0; p < 2; p++) {
            int idx = tid + p * NTH;
            int rA = idx >> 2, cA = (idx & 3) * 4;
            cpa16(ab + (unsigned)(rA * PAD_A + cA) * 4u, Ap + (size_t)(i0 + rA) * SL + kk + cA);
            int rB = idx >> 5, cB = (idx & 31) * 4;
            cpa16(b0 + (unsigned)(rB * PAD_B + cB) * 4u, B0p + (size_t)(kk + rB) * ED + cB);
            cpa16(b1 + (unsigned)(rB * PAD_B + cB) * 4u, B1p + (size_t)(kk + rB) * ED + cB);
        }
    };
    auto compute = [&](int s) {
        float* As = sm + s * STG_F;
        const unsigned* Bs0u = (const unsigned*)(As + SA);
        const unsigned* Bs1u = (const unsigned*)(As + SA + SB);
        unsigned abase = smaddr(As);
        #pragma unroll
        for (int kc = 0; kc < BK; kc += 8) {
            unsigned af[2][4];
            #pragma unroll
            for (int mt = 0; mt < 2; mt++) {
                int row = wm_ * 32 + mt * 16 + (lane & 7) + ((lane >> 3) & 1) * 8;
                int col = kc + (lane >> 4) * 4;
                ldsm4(af[mt][0], af[mt][1], af[mt][2], af[mt][3],
                      abase + (unsigned)(row * PAD_A + col) * 4u);
            }
            {
                unsigned bf[8][2];
                #pragma unroll
                for (int nt = 0; nt < 8; nt++) {
                    int n = wn_ * 64 + nt * 8 + (lane >> 2);
                    bf[nt][0] = Bs0u[(kc + (lane & 3)) * PAD_B + n];
                    bf[nt][1] = Bs0u[(kc + 4 + (lane & 3)) * PAD_B + n];
                }
                #pragma unroll
                for (int mt = 0; mt < 2; mt++)
                    #pragma unroll
                    for (int nt = 0; nt < 8; nt++)
                        mma8(acc0[mt][nt], af[mt][0], af[mt][1], af[mt][2], af[mt][3],
                             bf[nt][0], bf[nt][1]);
            }
            {
                unsigned bf[8][2];
                #pragma unroll
                for (int nt = 0; nt < 8; nt++) {
                    int n = wn_ * 64 + nt * 8 + (lane >> 2);
                    bf[nt][0] = Bs1u[(kc + (lane & 3)) * PAD_B + n];
                    bf[nt][1] = Bs1u[(kc + 4 + (lane & 3)) * PAD_B + n];
                }
                #pragma unroll
                for (int mt = 0; mt < 2; mt++)
                    #pragma unroll
                    for (int nt = 0; nt < 8; nt++)
                        mma8(acc1[mt][nt], af[mt][0], af[mt][1], af[mt][2], af[mt][3],
                             bf[nt][0], bf[nt][1]);
            }
        }
    };

    constexpr int NT = SL / BK;
    stage(0, 0); cpcommit();
    stage(1, BK); cpcommit();
    for (int t = 0; t < NT; t++) {
        cpwait<1>();
        __syncthreads();
        compute(t % 3);
        if (t + 2 < NT) stage((t + 2) % 3, (t + 2) * BK);
        cpcommit();
    }

    int r0 = lane >> 2, cc = (lane & 3) * 2;
    #pragma unroll
    for (int mt = 0; mt < 2; mt++) {
        #pragma unroll
        for (int half = 0; half < 2; half++) {
            int i = i0 + wm_ * 32 + mt * 16 + r0 + half * 8;
            size_t row = (size_t)b * SL + i;
            const float* uidr = Uid + row * ED;
            float* orow = outp + row * (4 * ED);
            #pragma unroll
            for (int nt = 0; nt < 8; nt++) {
                int e = wn_ * 64 + nt * 8 + cc;
                float2 uv = *(const float2*)(uidr + e);
                float ad0 = acc0[mt][nt][half * 2], ad1 = acc0[mt][nt][half * 2 + 1];
                float aq0 = acc1[mt][nt][half * 2], aq1 = acc1[mt][nt][half * 2 + 1];
                *(float2*)(orow + e) = uv;
                *(float2*)(orow + ED + e) = make_float2(ad0, ad1);
                *(float2*)(orow + 2 * ED + e) = make_float2(uv.x * ad0, uv.y * ad1);
                *(float2*)(orow + 3 * ED + e) = make_float2(uv.x * aq0, uv.y * aq1);
            }
        }
    }
}

// ---------------------------------------------------------------------------
extern "C" void kernel_launch(void* const* d_in, const int* in_sizes, int n_in,
                              void* d_out, int out_size) {
    const float* Uq   = (const float*)d_in[0];
    const float* Uid  = (const float*)d_in[1];
    const float* mask = (const float*)d_in[2];
    const float* Wcw  = (const float*)d_in[3];
    const float* Wcb  = (const float*)d_in[4];
    float* out = (float*)d_out;

    constexpr int SM_E = (3 * STG_E + 8 * BN) * 4;  // 65536
    constexpr int SM_T = 3 * STG_T * 4;             // 56832
    constexpr int SM_F = 3 * STG_F * 4;             // 82944
    cudaFuncSetAttribute(e_kernel, cudaFuncAttributeMaxDynamicSharedMemorySize, SM_E);
    cudaFuncSetAttribute(tn_kernel, cudaFuncAttributeMaxDynamicSharedMemorySize, SM_T);
    cudaFuncSetAttribute(nnf_kernel, cudaFuncAttributeMaxDynamicSharedMemorySize, SM_F);

    prep_kernel<<<NB * SL / 8, 256>>>(Uq, Uid, Wcw);
    e_kernel<<<dim3(NB, SL / BN, SL / BM), NTH, SM_E>>>(mask, Wcb);
    colsum_scale_kernel<<<NB * SL / 256, 256>>>(Uq);
    tn_kernel<<<dim3(1, NCH, NB), NTH, SM_T>>>();
    nnf_kernel<<<dim3(1, NCH, NB), NTH, SM_F>>>(Uid, out);
}

// round 5
// speedup vs baseline: 3.5885x; 1.0139x over previous
#include <cuda_runtime.h>

constexpr int NB = 8, SL = 2048, ED = 128;
constexpr int BK = 16;
constexpr int NTH = 256;
constexpr int PAD_A = 20;    // [m][k] ldmatrix stride -> conflict-free LDSM
constexpr int PAD_B = 136;   // [k][n=128] scalar stride (mod 32 == 8) -> conflict-free
constexpr int PAD_C = 72;    // [k][n=64]  scalar stride (mod 32 == 8) -> conflict-free
constexpr int NCH = 16;      // SL/128

// e_kernel (BM=BN=128): A,B both ldsm layout
constexpr int SA_E = 128 * PAD_A;            // 2560
constexpr int STG_E = 2 * SA_E;              // 5120
// tn (BM=64 over j, BN=128): A [k][64] pad 72, B [k][128] pad 136
constexpr int SA_T = BK * PAD_C;             // 1152
constexpr int SB_T = BK * PAD_B;             // 2176
constexpr int STG_T = SA_T + SB_T;           // 3328
// nnf (BM=128 over i, BN=64): A ldsm [128][k], two B [k][64] pad 72
constexpr int SA_F = 128 * PAD_A;            // 2560
constexpr int SB_F = BK * PAD_C;             // 1152
constexpr int STG_F = SA_F + 2 * SB_F;       // 4864

__device__ float g_E[(size_t)NB * SL * SL];
__device__ float g_c[NB * SL];
__device__ float g_cpart[NB * NCH * SL];
__device__ float g_sid[NB * SL];
__device__ float g_sq[NB * SL];
__device__ float g_Uidw[NB * SL * ED];
__device__ float g_Uqr[NB * SL * ED];
__device__ float g_Uidr[NB * SL * ED];
__device__ float g_Uqs[NB * SL * ED];
__device__ float g_Ts[NB * SL * ED];

// ---------------------------------------------------------------------------
__device__ __forceinline__ float tfr(float f) {
    unsigned u;
    asm("cvt.rna.tf32.f32 %0, %1;" : "=r"(u) : "f"(f));
    return __uint_as_float(u);
}
__device__ __forceinline__ void mma8(float* c, unsigned a0, unsigned a1, unsigned a2,
                                     unsigned a3, unsigned b0, unsigned b1) {
    asm volatile(
        "mma.sync.aligned.m16n8k8.row.col.f32.tf32.tf32.f32 "
        "{%0,%1,%2,%3},{%4,%5,%6,%7},{%8,%9},{%0,%1,%2,%3};"
        : "+f"(c[0]), "+f"(c[1]), "+f"(c[2]), "+f"(c[3])
        : "r"(a0), "r"(a1), "r"(a2), "r"(a3), "r"(b0), "r"(b1));
}
__device__ __forceinline__ void ldsm4(unsigned& r0, unsigned& r1, unsigned& r2,
                                      unsigned& r3, unsigned a) {
    asm volatile("ldmatrix.sync.aligned.m8n8.x4.shared.b16 {%0,%1,%2,%3},[%4];"
                 : "=r"(r0), "=r"(r1), "=r"(r2), "=r"(r3) : "r"(a));
}
__device__ __forceinline__ void cpa16(unsigned dst, const void* src) {
    asm volatile("cp.async.cg.shared.global [%0], [%1], 16;" :: "r"(dst), "l"(src));
}
__device__ __forceinline__ void cpcommit() { asm volatile("cp.async.commit_group;"); }
template <int N> __device__ __forceinline__ void cpwait() {
    asm volatile("cp.async.wait_group %0;" :: "n"(N));
}
__device__ __forceinline__ unsigned smaddr(const void* p) {
    return (unsigned)__cvta_generic_to_shared(p);
}

// ---------------------------------------------------------------------------
__global__ void prep_kernel(const float* __restrict__ Uq,
                            const float* __restrict__ Uid,
                            const float* __restrict__ Wc_w) {
    int gw = (blockIdx.x * blockDim.x + threadIdx.x) >> 5;
    int lane = threadIdx.x & 31;
    if (gw >= NB * SL) return;
    float4 a  = reinterpret_cast<const float4*>(Uid + (size_t)gw * ED)[lane];
    float4 q  = reinterpret_cast<const float4*>(Uq + (size_t)gw * ED)[lane];
    float4 w1 = reinterpret_cast<const float4*>(Wc_w)[lane];
    float4 w2 = reinterpret_cast<const float4*>(Wc_w + ED)[lane];
    float4 w3 = reinterpret_cast<const float4*>(Wc_w + 2 * ED)[lane];
    float s1 = a.x * w1.x + a.y * w1.y + a.z * w1.z + a.w * w1.w;
    float s2 = q.x * w2.x + q.y * w2.y + q.z * w2.z + q.w * w2.w;
    #pragma unroll
    for (int o = 16; o > 0; o >>= 1) {
        s1 += __shfl_xor_sync(0xffffffffu, s1, o);
        s2 += __shfl_xor_sync(0xffffffffu, s2, o);
    }
    if (lane == 0) { g_sid[gw] = s1; g_sq[gw] = s2; }
    float4 o1 = make_float4(tfr(a.x * w3.x), tfr(a.y * w3.y), tfr(a.z * w3.z), tfr(a.w * w3.w));
    float4 o2 = make_float4(tfr(q.x), tfr(q.y), tfr(q.z), tfr(q.w));
    float4 o3 = make_float4(tfr(a.x), tfr(a.y), tfr(a.z), tfr(a.w));
    reinterpret_cast<float4*>(g_Uidw + (size_t)gw * ED)[lane] = o1;
    reinterpret_cast<float4*>(g_Uqr  + (size_t)gw * ED)[lane] = o2;
    reinterpret_cast<float4*>(g_Uidr + (size_t)gw * ED)[lane] = o3;
}

// ---------------------------------------------------------------------------
// e_kernel: E = rna(exp((s_mul+s_id+s_q+b)*mask)) + fused column partials
// ---------------------------------------------------------------------------
__global__ void __launch_bounds__(NTH, 2)
e_kernel(const float* __restrict__ mask, const float* __restrict__ Wc_b) {
    extern __shared__ float sm[];
    int b = blockIdx.x, j0 = blockIdx.y * 128, i0 = blockIdx.z * 128;
    const float* Ap = g_Uidw + (size_t)b * SL * ED;
    const float* Bp = g_Uqr + (size_t)b * SL * ED;
    int tid = threadIdx.x, lane = tid & 31, wid = tid >> 5;
    int wm_ = wid & 3, wn_ = wid >> 2;
    float acc[2][8][4] = {};

    auto stage = [&](int s, int kk) {
        float* As = sm + s * STG_E;
        float* Bs = As + SA_E;
        unsigned ab = smaddr(As), bb = smaddr(Bs);
        #pragma unroll
        for (int p = 0; p < 2; p++) {
            int idx = tid + p * NTH;
            int r = idx >> 2, c = (idx & 3) * 4;
            cpa16(ab + (unsigned)(r * PAD_A + c) * 4u, Ap + (size_t)(i0 + r) * ED + kk + c);
            cpa16(bb + (unsigned)(r * PAD_A + c) * 4u, Bp + (size_t)(j0 + r) * ED + kk + c);
        }
    };
    auto compute = [&](int s) {
        float* As = sm + s * STG_E;
        float* Bs = As + SA_E;
        unsigned abase = smaddr(As), bbase = smaddr(Bs);
        #pragma unroll
        for (int kc = 0; kc < BK; kc += 8) {
            unsigned af[2][4];
            #pragma unroll
            for (int mt = 0; mt < 2; mt++) {
                int row = wm_ * 32 + mt * 16 + (lane & 7) + ((lane >> 3) & 1) * 8;
                int col = kc + (lane >> 4) * 4;
                ldsm4(af[mt][0], af[mt][1], af[mt][2], af[mt][3],
                      abase + (unsigned)(row * PAD_A + col) * 4u);
            }
            unsigned bf[8][2];
            #pragma unroll
            for (int np = 0; np < 4; np++) {
                int row = wn_ * 64 + np * 16 + ((lane >> 4) & 1) * 8 + (lane & 7);
                int col = kc + ((lane >> 3) & 1) * 4;
                ldsm4(bf[np * 2][0], bf[np * 2][1], bf[np * 2 + 1][0], bf[np * 2 + 1][1],
                      bbase + (unsigned)(row * PAD_A + col) * 4u);
            }
            #pragma unroll
            for (int mt = 0; mt < 2; mt++)
                #pragma unroll
                for (int nt = 0; nt < 8; nt++)
                    mma8(acc[mt][nt], af[mt][0], af[mt][1], af[mt][2], af[mt][3],
                         bf[nt][0], bf[nt][1]);
        }
    };

    constexpr int NT = ED / BK;
    stage(0, 0); cpcommit();
    stage(1, BK); cpcommit();
    for (int t = 0; t < NT; t++) {
        cpwait<1>();
        __syncthreads();
        compute(t % 3);
        if (t + 2 < NT) stage((t + 2) % 3, (t + 2) * BK);
        cpcommit();
    }

    float bias = Wc_b[0];
    float* Eout = g_E + (size_t)b * SL * SL;
    int r0 = lane >> 2, cc = (lane & 3) * 2;
    float csum[8][2];
    #pragma unroll
    for (int nt = 0; nt < 8; nt++) { csum[nt][0] = 0.f; csum[nt][1] = 0.f; }
    #pragma unroll
    for (int mt = 0; mt < 2; mt++) {
        #pragma unroll
        for (int half = 0; half < 2; half++) {
            int i = i0 + wm_ * 32 + mt * 16 + r0 + half * 8;
            float si = g_sid[b * SL + i] + bias;
            const float* mrow = mask + (size_t)i * SL;
            float* erow = Eout + (size_t)i * SL;
            #pragma unroll
            for (int nt = 0; nt < 8; nt++) {
                int j = j0 + wn_ * 64 + nt * 8 + cc;
                float2 mk = __ldg((const float2*)(mrow + j));
                float2 sq2 = *(const float2*)(&g_sq[b * SL + j]);
                float e0 = tfr(__expf((acc[mt][nt][half * 2 + 0] + si + sq2.x) * mk.x));
                float e1 = tfr(__expf((acc[mt][nt][half * 2 + 1] + si + sq2.y) * mk.y));
                __stcs((float2*)(erow + j), make_float2(e0, e1));
                csum[nt][0] += e0;
                csum[nt][1] += e1;
            }
        }
    }
    #pragma unroll
    for (int nt = 0; nt < 8; nt++) {
        #pragma unroll
        for (int d = 0; d < 2; d++) {
            float v = csum[nt][d];
            v += __shfl_xor_sync(0xffffffffu, v, 4);
            v += __shfl_xor_sync(0xffffffffu, v, 8);
            v += __shfl_xor_sync(0xffffffffu, v, 16);
            csum[nt][d] = v;
        }
    }
    float* red = sm + 3 * STG_E;
    if (lane < 4) {
        #pragma unroll
        for (int nt = 0; nt < 8; nt++) {
            red[wid * 128 + wn_ * 64 + nt * 8 + lane * 2 + 0] = csum[nt][0];
            red[wid * 128 + wn_ * 64 + nt * 8 + lane * 2 + 1] = csum[nt][1];
        }
    }
    __syncthreads();
    if (tid < 128) {
        int g = (tid >> 6) * 4;
        float s = red[(g + 0) * 128 + tid] + red[(g + 1) * 128 + tid] +
                  red[(g + 2) * 128 + tid] + red[(g + 3) * 128 + tid];
        g_cpart[((size_t)b * NCH + blockIdx.z) * SL + j0 + tid] = s;
    }
}

// ---------------------------------------------------------------------------
__global__ void __launch_bounds__(256)
colsum_scale_kernel(const float* __restrict__ Uq) {
    __shared__ float rcs[256];
    int tid = threadIdx.x;
    int base = blockIdx.x * 256;
    int idx = base + tid;
    int b = idx / SL, j = idx % SL;
    float s = 0.f;
    #pragma unroll
    for (int ch = 0; ch < NCH; ch++) s += g_cpart[((size_t)b * NCH + ch) * SL + j];
    g_c[idx] = s;
    rcs[tid] = 1.0f / s;
    __syncthreads();
    #pragma unroll
    for (int it = 0; it < 32; it++) {
        int flat = it * 256 + tid;
        int rl = flat >> 5, e4 = flat & 31;
        int row = base + rl;
        float rc = rcs[rl];
        float4 v = reinterpret_cast<const float4*>(Uq + (size_t)row * ED)[e4];
        v = make_float4(tfr(v.x * rc), tfr(v.y * rc), tfr(v.z * rc), tfr(v.w * rc));
        reinterpret_cast<float4*>(g_Uqs + (size_t)row * ED)[e4] = v;
    }
}

// ---------------------------------------------------------------------------
// TN: Ts[j,e] = rna((sum_i E[i,j]*Uid[i,e]) / c[j]^2); BM=64 over j -> 256 blocks
// warps: 2 (m) x 4 (n); A [k][64] pad 72; B [k][128] pad 136
// ---------------------------------------------------------------------------
__global__ void __launch_bounds__(NTH, 2)
tn_kernel() {
    extern __shared__ float sm[];
    int b = blockIdx.x, j0 = blockIdx.y * 64;
    const float* Ap = g_E + (size_t)b * SL * SL;
    const float* Bp = g_Uidr + (size_t)b * SL * ED;
    int tid = threadIdx.x, lane = tid & 31, wid = tid >> 5;
    int wm_ = wid & 1, wn_ = wid >> 1;
    float acc[2][4][4] = {};

    auto stage = [&](int s, int kk) {
        float* As = sm + s * STG_T;          // [k][64] pad 72
        float* Bs = As + SA_T;               // [k][128] pad 136
        unsigned ab = smaddr(As), bb = smaddr(Bs);
        #pragma unroll
        for (int p = 0; p < 3; p++) {
            int idx = tid + p * NTH;         // 0..767: first 512 B, last 256 A
            if (idx < 512) {
                int r = idx >> 5, c = (idx & 31) * 4;
                cpa16(bb + (unsigned)(r * PAD_B + c) * 4u, Bp + (size_t)(kk + r) * ED + c);
            } else {
                int a = idx - 512;
                int r = a >> 4, c = (a & 15) * 4;
                cpa16(ab + (unsigned)(r * PAD_C + c) * 4u, Ap + (size_t)(kk + r) * SL + j0 + c);
            }
        }
    };
    auto compute = [&](int s) {
        const unsigned* Asu = (const unsigned*)(sm + s * STG_T);
        const unsigned* Bsu = (const unsigned*)(sm + s * STG_T + SA_T);
        #pragma unroll
        for (int kc = 0; kc < BK; kc += 8) {
            unsigned af[2][4];
            #pragma unroll
            for (int mt = 0; mt < 2; mt++) {
                int m = wm_ * 32 + mt * 16 + (lane >> 2);
                af[mt][0] = Asu[(kc + (lane & 3)) * PAD_C + m];
                af[mt][1] = Asu[(kc + (lane & 3)) * PAD_C + m + 8];
                af[mt][2] = Asu[(kc + 4 + (lane & 3)) * PAD_C + m];
                af[mt][3] = Asu[(kc + 4 + (lane & 3)) * PAD_C + m + 8];
            }
            unsigned bf[4][2];
            #pragma unroll
            for (int nt = 0; nt < 4; nt++) {
                int n = wn_ * 32 + nt * 8 + (lane >> 2);
                bf[nt][0] = Bsu[(kc + (lane & 3)) * PAD_B + n];
                bf[nt][1] = Bsu[(kc + 4 + (lane & 3)) * PAD_B + n];
            }
            #pragma unroll
            for (int mt = 0; mt < 2; mt++)
                #pragma unroll
                for (int nt = 0; nt < 4; nt++)
                    mma8(acc[mt][nt], af[mt][0], af[mt][1], af[mt][2], af[mt][3],
                         bf[nt][0], bf[nt][1]);
        }
    };

    constexpr int NT = SL / BK;
    stage(0, 0); cpcommit();
    stage(1, BK); cpcommit();
    for (int t = 0; t < NT; t++) {
        cpwait<1>();
        __syncthreads();
        compute(t % 3);
        if (t + 2 < NT) stage((t + 2) % 3, (t + 2) * BK);
        cpcommit();
    }

    int r0 = lane >> 2, cc = (lane & 3) * 2;
    #pragma unroll
    for (int mt = 0; mt < 2; mt++) {
        #pragma unroll
        for (int half = 0; half < 2; half++) {
            int j = j0 + wm_ * 32 + mt * 16 + r0 + half * 8;
            float cj = g_c[b * SL + j];
            float s = 1.0f / (cj * cj);
            float* orow = g_Ts + ((size_t)b * SL + j) * ED;
            #pragma unroll
            for (int nt = 0; nt < 4; nt++) {
                int e = wn_ * 32 + nt * 8 + cc;
                *(float2*)(orow + e) = make_float2(tfr(acc[mt][nt][half * 2] * s),
                                                   tfr(acc[mt][nt][half * 2 + 1] * s));
            }
        }
    }
}

// ---------------------------------------------------------------------------
// Fused NN: A_D2Q = E@Uqs and A_Q2D = E@Ts + assembled output.
// BM=128 over i, BN=64 (two n-halves) -> 256 blocks, 2 CTAs/SM.
// warps: 4 (m) x 2 (n); A ldsm [128][k]; B0/B1 [k][64] pad 72
// ---------------------------------------------------------------------------
__global__ void __launch_bounds__(NTH, 2)
nnf_kernel(const float* __restrict__ Uid, float* __restrict__ outp) {
    extern __shared__ float sm[];
    int b = blockIdx.x >> 1, n0 = (blockIdx.x & 1) * 64;
    int i0 = blockIdx.y * 128;
    const float* Ap = g_E + (size_t)b * SL * SL;
    const float* B0p = g_Uqs + (size_t)b * SL * ED + n0;
    const float* B1p = g_Ts + (size_t)b * SL * ED + n0;
    int tid = threadIdx.x, lane = tid & 31, wid = tid >> 5;
    int wm_ = wid & 3, wn_ = wid >> 2;
    float acc0[2][4][4] = {};
    float acc1[2][4][4] = {};

    auto stage = [&](int s, int kk) {
        float* As = sm + s * STG_F;
        float* Bs0 = As + SA_F;
        float* Bs1 = Bs0 + SB_F;
        unsigned ab = smaddr(As), b0 = smaddr(Bs0), b1 = smaddr(Bs1);
        #pragma unroll
        for (int p = 0; p < 4; p++) {
            int idx = tid + p * NTH;  // 0..1023: 512 A, 256 B0, 256 B1
            if (idx < 512) {
                int rA = idx >> 2, cA = (idx & 3) * 4;
                cpa16(ab + (unsigned)(rA * PAD_A + cA) * 4u,
                      Ap + (size_t)(i0 + rA) * SL + kk + cA);
            } else {
                int q = idx - 512;
                int r = (q & 255) >> 4, c = (q & 15) * 4;
                unsigned dst = (q < 256 ? b0 : b1) + (unsigned)(r * PAD_C + c) * 4u;
                const float* src = (q < 256 ? B0p : B1p) + (size_t)(kk + r) * ED + c;
                cpa16(dst, src);
            }
        }
    };
    auto compute = [&](int s) {
        float* As = sm + s * STG_F;
        const unsigned* Bs0u = (const unsigned*)(As + SA_F);
        const unsigned* Bs1u = (const unsigned*)(As + SA_F + SB_F);
        unsigned abase = smaddr(As);
        #pragma unroll
        for (int kc = 0; kc < BK; kc += 8) {
            unsigned af[2][4];
            #pragma unroll
            for (int mt = 0; mt < 2; mt++) {
                int row = wm_ * 32 + mt * 16 + (lane & 7) + ((lane >> 3) & 1) * 8;
                int col = kc + (lane >> 4) * 4;
                ldsm4(af[mt][0], af[mt][1], af[mt][2], af[mt][3],
                      abase + (unsigned)(row * PAD_A + col) * 4u);
            }
            {
                unsigned bf[4][2];
                #pragma unroll
                for (int nt = 0; nt < 4; nt++) {
                    int n = wn_ * 32 + nt * 8 + (lane >> 2);
                    bf[nt][0] = Bs0u[(kc + (lane & 3)) * PAD_C + n];
                    bf[nt][1] = Bs0u[(kc + 4 + (lane & 3)) * PAD_C + n];
                }
                #pragma unroll
                for (int mt = 0; mt < 2; mt++)
                    #pragma unroll
                    for (int nt = 0; nt < 4; nt++)
                        mma8(acc0[mt][nt], af[mt][0], af[mt][1], af[mt][2], af[mt][3],
                             bf[nt][0], bf[nt][1]);
            }
            {
                unsigned bf[4][2];
                #pragma unroll
                for (int nt = 0; nt < 4; nt++) {
                    int n = wn_ * 32 + nt * 8 + (lane >> 2);
                    bf[nt][0] = Bs1u[(kc + (lane & 3)) * PAD_C + n];
                    bf[nt][1] = Bs1u[(kc + 4 + (lane & 3)) * PAD_C + n];
                }
                #pragma unroll
                for (int mt = 0; mt < 2; mt++)
                    #pragma unroll
                    for (int nt = 0; nt < 4; nt++)
                        mma8(acc1[mt][nt], af[mt][0], af[mt][1], af[mt][2], af[mt][3],
                             bf[nt][0], bf[nt][1]);
            }
        }
    };

    constexpr int NT = SL / BK;
    stage(0, 0); cpcommit();
    stage(1, BK); cpcommit();
    for (int t = 0; t < NT; t++) {
        cpwait<1>();
        __syncthreads();
        compute(t % 3);
        if (t + 2 < NT) stage((t + 2) % 3, (t + 2) * BK);
        cpcommit();
    }

    int r0 = lane >> 2, cc = (lane & 3) * 2;
    #pragma unroll
    for (int mt = 0; mt < 2; mt++) {
        #pragma unroll
        for (int half = 0; half < 2; half++) {
            int i = i0 + wm_ * 32 + mt * 16 + r0 + half * 8;
            size_t row = (size_t)b * SL + i;
            const float* uidr = Uid + row * ED;
            float* orow = outp + row * (4 * ED);
            #pragma unroll
            for (int nt = 0; nt < 4; nt++) {
                int e = n0 + wn_ * 32 + nt * 8 + cc;
                float2 uv = *(const float2*)(uidr + e);
                float ad0 = acc0[mt][nt][half * 2], ad1 = acc0[mt][nt][half * 2 + 1];
                float aq0 = acc1[mt][nt][half * 2], aq1 = acc1[mt][nt][half * 2 + 1];
                *(float2*)(orow + e) = uv;
                *(float2*)(orow + ED + e) = make_float2(ad0, ad1);
                *(float2*)(orow + 2 * ED + e) = make_float2(uv.x * ad0, uv.y * ad1);
                *(float2*)(orow + 3 * ED + e) = make_float2(uv.x * aq0, uv.y * aq1);
            }
        }
    }
}

// ---------------------------------------------------------------------------
extern "C" void kernel_launch(void* const* d_in, const int* in_sizes, int n_in,
                              void* d_out, int out_size) {
    const float* Uq   = (const float*)d_in[0];
    const float* Uid  = (const float*)d_in[1];
    const float* mask = (const float*)d_in[2];
    const float* Wcw  = (const float*)d_in[3];
    const float* Wcb  = (const float*)d_in[4];
    float* out = (float*)d_out;

    constexpr int SM_E = (3 * STG_E + 8 * 128) * 4;  // 65536
    constexpr int SM_T = 3 * STG_T * 4;              // 39936
    constexpr int SM_F = 3 * STG_F * 4;              // 58368
    cudaFuncSetAttribute(e_kernel, cudaFuncAttributeMaxDynamicSharedMemorySize, SM_E);
    cudaFuncSetAttribute(tn_kernel, cudaFuncAttributeMaxDynamicSharedMemorySize, SM_T);
    cudaFuncSetAttribute(nnf_kernel, cudaFuncAttributeMaxDynamicSharedMemorySize, SM_F);

    prep_kernel<<<NB * SL / 8, 256>>>(Uq, Uid, Wcw);
    e_kernel<<<dim3(NB, SL / 128, SL / 128), NTH, SM_E>>>(mask, Wcb);
    colsum_scale_kernel<<<NB * SL / 256, 256>>>(Uq);
    tn_kernel<<<dim3(NB, SL / 64), NTH, SM_T>>>();
    nnf_kernel<<<dim3(2 * NB, SL / 128), NTH, SM_F>>>(Uid, out);
}

// round 7
// speedup vs baseline: 5.5673x; 1.5514x over previous
#include <cuda_runtime.h>
#include <cuda_fp16.h>

constexpr int NB = 8, SL = 2048, ED = 128;
constexpr int BKH = 32;      // k-tile (elements)
constexpr int NTH = 256;
constexpr int NCH = 16;      // SL/128 column-sum chunks
// smem row strides (halves); 16*odd byte strides -> conflict-free LDSM
constexpr int PADE = 40;     // [m][32] tiles (80 B)
constexpr int PADT = 72;     // [k][64] tiles (144 B)
constexpr int PADB = 136;    // [k][128] tiles (272 B)

constexpr int SA_E = 128 * PADE;            // 5120 halves
constexpr int STG_E = 2 * SA_E;             // 10240
constexpr int SA_T = 32 * PADT;             // 2304 (E^T tile [k][64])
constexpr int SB_T = 32 * PADB;             // 4352 (Uid  tile [k][128])
constexpr int STG_T = SA_T + SB_T;          // 6656
constexpr int SA_F = 64 * PADE;             // 2560 (E tile [m=64][k=32])
constexpr int SB_F = 32 * PADB;             // 4352 ([k=32][n=128])
constexpr int STG_F = SA_F + 2 * SB_F;      // 11264

__device__ __half g_EH[(size_t)NB * SL * SL];   // exp(S), fp16 (64 MiB)
__device__ float g_c[NB * SL];
__device__ float g_cpart[NB * NCH * SL];
__device__ float g_sid[NB * SL];
__device__ float g_sq[NB * SL];
__device__ __half g_UidwH[NB * SL * ED];  // rn(Uid .* w_mul)
__device__ __half g_UqrH[NB * SL * ED];   // rn(Uq)
__device__ __half g_UidrH[NB * SL * ED];  // rn(Uid)
__device__ __half g_UqsH[NB * SL * ED];   // rn(Uq / c * 1024)
__device__ __half g_TsH[NB * SL * ED];    // rn((E^T Uid) / c^2 * 1024)

// ---------------------------------------------------------------------------
__device__ __forceinline__ void mma16(float* c, unsigned a0, unsigned a1, unsigned a2,
                                      unsigned a3, unsigned b0, unsigned b1) {
    asm volatile(
        "mma.sync.aligned.m16n8k16.row.col.f32.f16.f16.f32 "
        "{%0,%1,%2,%3},{%4,%5,%6,%7},{%8,%9},{%0,%1,%2,%3};"
        : "+f"(c[0]), "+f"(c[1]), "+f"(c[2]), "+f"(c[3])
        : "r"(a0), "r"(a1), "r"(a2), "r"(a3), "r"(b0), "r"(b1));
}
__device__ __forceinline__ void ldsm4(unsigned& r0, unsigned& r1, unsigned& r2,
                                      unsigned& r3, unsigned a) {
    asm volatile("ldmatrix.sync.aligned.m8n8.x4.shared.b16 {%0,%1,%2,%3},[%4];"
                 : "=r"(r0), "=r"(r1), "=r"(r2), "=r"(r3) : "r"(a));
}
__device__ __forceinline__ void ldsm4t(unsigned& r0, unsigned& r1, unsigned& r2,
                                       unsigned& r3, unsigned a) {
    asm volatile("ldmatrix.sync.aligned.m8n8.x4.trans.shared.b16 {%0,%1,%2,%3},[%4];"
                 : "=r"(r0), "=r"(r1), "=r"(r2), "=r"(r3) : "r"(a));
}
__device__ __forceinline__ void cpa16(unsigned dst, const void* src) {
    asm volatile("cp.async.cg.shared.global [%0], [%1], 16;" :: "r"(dst), "l"(src));
}
__device__ __forceinline__ void cpcommit() { asm volatile("cp.async.commit_group;"); }
template <int N> __device__ __forceinline__ void cpwait() {
    asm volatile("cp.async.wait_group %0;" :: "n"(N));
}
__device__ __forceinline__ unsigned smaddr(const void* p) {
    return (unsigned)__cvta_generic_to_shared(p);
}

// ---------------------------------------------------------------------------
// prep: s_id, s_q (fp32), plus fp16 operand copies
// ---------------------------------------------------------------------------
__global__ void prep_kernel(const float* __restrict__ Uq,
                            const float* __restrict__ Uid,
                            const float* __restrict__ Wc_w) {
    int gw = (blockIdx.x * blockDim.x + threadIdx.x) >> 5;
    int lane = threadIdx.x & 31;
    if (gw >= NB * SL) return;
    float4 a  = reinterpret_cast<const float4*>(Uid + (size_t)gw * ED)[lane];
    float4 q  = reinterpret_cast<const float4*>(Uq + (size_t)gw * ED)[lane];
    float4 w1 = reinterpret_cast<const float4*>(Wc_w)[lane];
    float4 w2 = reinterpret_cast<const float4*>(Wc_w + ED)[lane];
    float4 w3 = reinterpret_cast<const float4*>(Wc_w + 2 * ED)[lane];
    float s1 = a.x * w1.x + a.y * w1.y + a.z * w1.z + a.w * w1.w;
    float s2 = q.x * w2.x + q.y * w2.y + q.z * w2.z + q.w * w2.w;
    #pragma unroll
    for (int o = 16; o > 0; o >>= 1) {
        s1 += __shfl_xor_sync(0xffffffffu, s1, o);
        s2 += __shfl_xor_sync(0xffffffffu, s2, o);
    }
    if (lane == 0) { g_sid[gw] = s1; g_sq[gw] = s2; }
    __half2* d1 = (__half2*)(g_UidwH + (size_t)gw * ED);
    __half2* d2 = (__half2*)(g_UqrH  + (size_t)gw * ED);
    __half2* d3 = (__half2*)(g_UidrH + (size_t)gw * ED);
    d1[lane * 2]     = __floats2half2_rn(a.x * w3.x, a.y * w3.y);
    d1[lane * 2 + 1] = __floats2half2_rn(a.z * w3.z, a.w * w3.w);
    d2[lane * 2]     = __floats2half2_rn(q.x, q.y);
    d2[lane * 2 + 1] = __floats2half2_rn(q.z, q.w);
    d3[lane * 2]     = __floats2half2_rn(a.x, a.y);
    d3[lane * 2 + 1] = __floats2half2_rn(a.z, a.w);
}

// ---------------------------------------------------------------------------
// e_kernel: E = rn_fp16(exp((s_mul+s_id+s_q+b)*mask)) + fused column partials
// A = Uidw [m][k], B = Uqr [n][k], both fp16, non-trans ldsm
// ---------------------------------------------------------------------------
__global__ void __launch_bounds__(NTH, 2)
e_kernel(const float* __restrict__ mask, const float* __restrict__ Wc_b) {
    extern __shared__ __half smh[];
    int b = blockIdx.x, j0 = blockIdx.y * 128, i0 = blockIdx.z * 128;
    const __half* Ap = g_UidwH + (size_t)b * SL * ED;
    const __half* Bp = g_UqrH + (size_t)b * SL * ED;
    int tid = threadIdx.x, lane = tid & 31, wid = tid >> 5;
    int wm_ = wid & 3, wn_ = wid >> 2;  // 4 m-warps x 2 n-warps; warp tile 32x64
    float acc[2][8][4] = {};

    auto stage = [&](int s, int kk) {
        __half* As = smh + s * STG_E;
        __half* Bs = As + SA_E;
        unsigned ab = smaddr(As), bb = smaddr(Bs);
        #pragma unroll
        for (int p = 0; p < 2; p++) {
            int idx = tid + p * NTH;
            int r = idx >> 2, c = (idx & 3) * 8;
            cpa16(ab + (unsigned)(r * PADE + c) * 2u, Ap + (size_t)(i0 + r) * ED + kk + c);
            cpa16(bb + (unsigned)(r * PADE + c) * 2u, Bp + (size_t)(j0 + r) * ED + kk + c);
        }
    };
    auto compute = [&](int s) {
        unsigned abase = smaddr(smh + s * STG_E);
        unsigned bbase = abase + SA_E * 2;
        #pragma unroll
        for (int kc = 0; kc < BKH; kc += 16) {
            int col = kc + ((lane >> 4) & 1) * 8;
            unsigned af[2][4];
            #pragma unroll
            for (int mt = 0; mt < 2; mt++) {
                int row = wm_ * 32 + mt * 16 + (lane & 7) + ((lane >> 3) & 1) * 8;
                ldsm4(af[mt][0], af[mt][1], af[mt][2], af[mt][3],
                      abase + (unsigned)(row * PADE + col) * 2u);
            }
            #pragma unroll
            for (int np = 0; np < 4; np++) {
                int row = wn_ * 64 + np * 16 + (lane & 7) + ((lane >> 3) & 1) * 8;
                unsigned r0, r1, r2, r3;
                ldsm4(r0, r1, r2, r3, bbase + (unsigned)(row * PADE + col) * 2u);
                #pragma unroll
                for (int mt = 0; mt < 2; mt++) {
                    mma16(acc[mt][np * 2 + 0], af[mt][0], af[mt][1], af[mt][2], af[mt][3], r0, r2);
                    mma16(acc[mt][np * 2 + 1], af[mt][0], af[mt][1], af[mt][2], af[mt][3], r1, r3);
                }
            }
        }
    };

    constexpr int NT = ED / BKH;  // 4
    stage(0, 0); cpcommit();
    stage(1, BKH); cpcommit();
    for (int t = 0; t < NT; t++) {
        cpwait<1>();
        __syncthreads();
        compute(t % 3);
        if (t + 2 < NT) stage((t + 2) % 3, (t + 2) * BKH);
        cpcommit();
    }

    float bias = Wc_b[0];
    __half* Eout = g_EH + (size_t)b * SL * SL;
    int r0 = lane >> 2, cc = (lane & 3) * 2;
    float csum[8][2];
    #pragma unroll
    for (int nt = 0; nt < 8; nt++) { csum[nt][0] = 0.f; csum[nt][1] = 0.f; }
    #pragma unroll
    for (int mt = 0; mt < 2; mt++) {
        #pragma unroll
        for (int half_ = 0; half_ < 2; half_++) {
            int i = i0 + wm_ * 32 + mt * 16 + r0 + half_ * 8;
            float si = g_sid[b * SL + i] + bias;
            const float* mrow = mask + (size_t)i * SL;
            __half* erow = Eout + (size_t)i * SL;
            #pragma unroll
            for (int nt = 0; nt < 8; nt++) {
                int j = j0 + wn_ * 64 + nt * 8 + cc;
                float2 mk = __ldg((const float2*)(mrow + j));
                float2 sq2 = *(const float2*)(&g_sq[b * SL + j]);
                __half h0 = __float2half_rn(__expf((acc[mt][nt][half_ * 2 + 0] + si + sq2.x) * mk.x));
                __half h1 = __float2half_rn(__expf((acc[mt][nt][half_ * 2 + 1] + si + sq2.y) * mk.y));
                *(__half2*)(erow + j) = __halves2half2(h0, h1);
                csum[nt][0] += __half2float(h0);
                csum[nt][1] += __half2float(h1);
            }
        }
    }
    #pragma unroll
    for (int nt = 0; nt < 8; nt++) {
        #pragma unroll
        for (int d = 0; d < 2; d++) {
            float v = csum[nt][d];
            v += __shfl_xor_sync(0xffffffffu, v, 4);
            v += __shfl_xor_sync(0xffffffffu, v, 8);
            v += __shfl_xor_sync(0xffffffffu, v, 16);
            csum[nt][d] = v;
        }
    }
    float* red = (float*)(smh + 3 * STG_E);
    if (lane < 4) {
        #pragma unroll
        for (int nt = 0; nt < 8; nt++) {
            red[wid * 128 + wn_ * 64 + nt * 8 + lane * 2 + 0] = csum[nt][0];
            red[wid * 128 + wn_ * 64 + nt * 8 + lane * 2 + 1] = csum[nt][1];
        }
    }
    __syncthreads();
    if (tid < 128) {
        int g = (tid >> 6) * 4;
        float s = red[(g + 0) * 128 + tid] + red[(g + 1) * 128 + tid] +
                  red[(g + 2) * 128 + tid] + red[(g + 3) * 128 + tid];
        g_cpart[((size_t)b * NCH + blockIdx.z) * SL + j0 + tid] = s;
    }
}

// ---------------------------------------------------------------------------
// colsum finish + Uqs' = rn_fp16(Uq / c * 1024)
// ---------------------------------------------------------------------------
__global__ void __launch_bounds__(256)
colsum_scale_kernel(const float* __restrict__ Uq) {
    __shared__ float rcs[256];
    int tid = threadIdx.x;
    int base = blockIdx.x * 256;
    int idx = base + tid;
    int b = idx / SL, j = idx % SL;
    float s = 0.f;
    #pragma unroll
    for (int ch = 0; ch < NCH; ch++) s += g_cpart[((size_t)b * NCH + ch) * SL + j];
    g_c[idx] = s;
    rcs[tid] = 1024.0f / s;
    __syncthreads();
    #pragma unroll
    for (int it = 0; it < 32; it++) {
        int flat = it * 256 + tid;
        int rl = flat >> 5, e4 = flat & 31;
        int row = base + rl;
        float rc = rcs[rl];
        float4 v = reinterpret_cast<const float4*>(Uq + (size_t)row * ED)[e4];
        __half2* op = (__half2*)(g_UqsH + (size_t)row * ED);
        op[e4 * 2]     = __floats2half2_rn(v.x * rc, v.y * rc);
        op[e4 * 2 + 1] = __floats2half2_rn(v.z * rc, v.w * rc);
    }
}

// ---------------------------------------------------------------------------
// TN: Ts'[j,e] = rn_fp16( (sum_i E[i,j]*Uid[i,e]) * 1024 / c[j]^2 )
// A = E^T via ldsm.trans on [k=i][j]; B = Uidr via ldsm.trans on [k][e]
// BM=64 j-rows -> 256 blocks; warps 2(m) x 4(n), tile 32x32
// ---------------------------------------------------------------------------
__global__ void __launch_bounds__(NTH, 2)
tn_kernel() {
    extern __shared__ __half smh[];
    int b = blockIdx.x, j0 = blockIdx.y * 64;
    const __half* Ap = g_EH + (size_t)b * SL * SL;
    const __half* Bp = g_UidrH + (size_t)b * SL * ED;
    int tid = threadIdx.x, lane = tid & 31, wid = tid >> 5;
    int wm_ = wid & 1, wn_ = wid >> 1;
    float acc[2][4][4] = {};

    auto stage = [&](int s, int kk) {
        __half* As = smh + s * STG_T;      // [k=32][m=64] stride 72
        __half* Bs = As + SA_T;            // [k=32][n=128] stride 136
        unsigned ab = smaddr(As), bb = smaddr(Bs);
        #pragma unroll
        for (int p = 0; p < 3; p++) {
            int idx = tid + p * NTH;       // 768: 256 A + 512 B
            if (idx < 256) {
                int r = idx >> 3, c = (idx & 7) * 8;
                cpa16(ab + (unsigned)(r * PADT + c) * 2u,
                      Ap + (size_t)(kk + r) * SL + j0 + c);
            } else {
                int q = idx - 256;
                int r = q >> 4, c = (q & 15) * 8;
                cpa16(bb + (unsigned)(r * PADB + c) * 2u,
                      Bp + (size_t)(kk + r) * ED + c);
            }
        }
    };
    auto compute = [&](int s) {
        unsigned abase = smaddr(smh + s * STG_T);
        unsigned bbase = abase + SA_T * 2;
        #pragma unroll
        for (int kc = 0; kc < BKH; kc += 16) {
            unsigned af[2][4];
            #pragma unroll
            for (int mt = 0; mt < 2; mt++) {
                int row = kc + ((lane >> 4) & 1) * 8 + (lane & 7);
                int col = wm_ * 32 + mt * 16 + ((lane >> 3) & 1) * 8;
                ldsm4t(af[mt][0], af[mt][1], af[mt][2], af[mt][3],
                       abase + (unsigned)(row * PADT + col) * 2u);
            }
            #pragma unroll
            for (int np = 0; np < 2; np++) {
                int row = kc + ((lane >> 3) & 1) * 8 + (lane & 7);
                int col = wn_ * 32 + np * 16 + ((lane >> 4) & 1) * 8;
                unsigned r0, r1, r2, r3;
                ldsm4t(r0, r1, r2, r3, bbase + (unsigned)(row * PADB + col) * 2u);
                #pragma unroll
                for (int mt = 0; mt < 2; mt++) {
                    mma16(acc[mt][np * 2 + 0], af[mt][0], af[mt][1], af[mt][2], af[mt][3], r0, r1);
                    mma16(acc[mt][np * 2 + 1], af[mt][0], af[mt][1], af[mt][2], af[mt][3], r2, r3);
                }
            }
        }
    };

    constexpr int NT = SL / BKH;  // 64
    stage(0, 0); cpcommit();
    stage(1, BKH); cpcommit();
    for (int t = 0; t < NT; t++) {
        cpwait<1>();
        __syncthreads();
        compute(t % 3);
        if (t + 2 < NT) stage((t + 2) % 3, (t + 2) * BKH);
        cpcommit();
    }

    int r0 = lane >> 2, cc = (lane & 3) * 2;
    #pragma unroll
    for (int mt = 0; mt < 2; mt++) {
        #pragma unroll
        for (int half_ = 0; half_ < 2; half_++) {
            int j = j0 + wm_ * 32 + mt * 16 + r0 + half_ * 8;
            float cj = g_c[b * SL + j];
            float s = 1024.0f / (cj * cj);
            __half* orow = g_TsH + ((size_t)b * SL + j) * ED;
            #pragma unroll
            for (int nt = 0; nt < 4; nt++) {
                int e = wn_ * 32 + nt * 8 + cc;
                *(__half2*)(orow + e) = __floats2half2_rn(acc[mt][nt][half_ * 2] * s,
                                                          acc[mt][nt][half_ * 2 + 1] * s);
            }
        }
    }
}

// ---------------------------------------------------------------------------
// Fused NN: acc0 = E@Uqs', acc1 = E@Ts' (one E pass), assembled output /1024
// BM=64 i-rows, BN=128 -> 256 blocks; warps 2(m) x 4(n)
// A ldsm [m=64][k=32] stride PADE; B0/B1 ldsm.trans [k=32][n=128] stride PADB
// ---------------------------------------------------------------------------
__global__ void __launch_bounds__(NTH, 2)
nnf_kernel(const float* __restrict__ Uid, float* __restrict__ outp) {
    extern __shared__ __half smh[];
    int b = blockIdx.x, i0 = blockIdx.y * 64;
    const __half* Ap = g_EH + (size_t)b * SL * SL;
    const __half* B0p = g_UqsH + (size_t)b * SL * ED;
    const __half* B1p = g_TsH + (size_t)b * SL * ED;
    int tid = threadIdx.x, lane = tid & 31, wid = tid >> 5;
    int wm_ = wid & 1, wn_ = wid >> 1;
    float acc0[2][4][4] = {};
    float acc1[2][4][4] = {};

    auto stage = [&](int s, int kk) {
        __half* As = smh + s * STG_F;       // [m=64][k=32] stride 40
        __half* Bs0 = As + SA_F;            // [k=32][n=128] stride 136
        __half* Bs1 = Bs0 + SB_F;
        unsigned ab = smaddr(As), b0 = smaddr(Bs0), b1 = smaddr(Bs1);
        #pragma unroll
        for (int p = 0; p < 5; p++) {
            int idx = tid + p * NTH;        // 1280: 256 A + 512 B0 + 512 B1
            if (idx < 256) {
                int r = idx >> 2, c = (idx & 3) * 8;
                cpa16(ab + (unsigned)(r * PADE + c) * 2u,
                      Ap + (size_t)(i0 + r) * SL + kk + c);
            } else {
                int q = (idx - 256) & 511;
                int r = q >> 4, c = (q & 15) * 8;
                unsigned dst = (idx < 768 ? b0 : b1) + (unsigned)(r * PADB + c) * 2u;
                const __half* src = (idx < 768 ? B0p : B1p) + (size_t)(kk + r) * ED + c;
                cpa16(dst, src);
            }
        }
    };
    auto compute = [&](int s) {
        unsigned abase = smaddr(smh + s * STG_F);
        unsigned b0base = abase + SA_F * 2;
        unsigned b1base = b0base + SB_F * 2;
        #pragma unroll
        for (int kc = 0; kc < BKH; kc += 16) {
            unsigned af[2][4];
            #pragma unroll
            for (int mt = 0; mt < 2; mt++) {
                int row = wm_ * 32 + mt * 16 + (lane & 7) + ((lane >> 3) & 1) * 8;
                int col = kc + ((lane >> 4) & 1) * 8;
                ldsm4(af[mt][0], af[mt][1], af[mt][2], af[mt][3],
                      abase + (unsigned)(row * PADE + col) * 2u);
            }
            #pragma unroll
            for (int np = 0; np < 2; np++) {
                int row = kc + ((lane >> 3) & 1) * 8 + (lane & 7);
                int col = wn_ * 32 + np * 16 + ((lane >> 4) & 1) * 8;
                unsigned r0, r1, r2, r3;
                ldsm4t(r0, r1, r2, r3, b0base + (unsigned)(row * PADB + col) * 2u);
                #pragma unroll
                for (int mt = 0; mt < 2; mt++) {
                    mma16(acc0[mt][np * 2 + 0], af[mt][0], af[mt][1], af[mt][2], af[mt][3], r0, r1);
                    mma16(acc0[mt][np * 2 + 1], af[mt][0], af[mt][1], af[mt][2], af[mt][3], r2, r3);
                }
                ldsm4t(r0, r1, r2, r3, b1base + (unsigned)(row * PADB + col) * 2u);
                #pragma unroll
                for (int mt = 0; mt < 2; mt++) {
                    mma16(acc1[mt][np * 2 + 0], af[mt][0], af[mt][1], af[mt][2], af[mt][3], r0, r1);
                    mma16(acc1[mt][np * 2 + 1], af[mt][0], af[mt][1], af[mt][2], af[mt][3], r2, r3);
                }
            }
        }
    };

    constexpr int NT = SL / BKH;  // 64
    stage(0, 0); cpcommit();
    stage(1, BKH); cpcommit();
    for (int t = 0; t < NT; t++) {
        cpwait<1>();
        __syncthreads();
        compute(t % 3);
        if (t + 2 < NT) stage((t + 2) % 3, (t + 2) * BKH);
        cpcommit();
    }

    constexpr float INV = 1.0f / 1024.0f;
    int r0 = lane >> 2, cc = (lane & 3) * 2;
    #pragma unroll
    for (int mt = 0; mt < 2; mt++) {
        #pragma unroll
        for (int half_ = 0; half_ < 2; half_++) {
            int i = i0 + wm_ * 32 + mt * 16 + r0 + half_ * 8;
            size_t row = (size_t)b * SL + i;
            const float* uidr = Uid + row * ED;
            float* orow = outp + row * (4 * ED);
            #pragma unroll
            for (int nt = 0; nt < 4; nt++) {
                int e = wn_ * 32 + nt * 8 + cc;
                float2 uv = *(const float2*)(uidr + e);
                float ad0 = acc0[mt][nt][half_ * 2] * INV, ad1 = acc0[mt][nt][half_ * 2 + 1] * INV;
                float aq0 = acc1[mt][nt][half_ * 2] * INV, aq1 = acc1[mt][nt][half_ * 2 + 1] * INV;
                *(float2*)(orow + e) = uv;
                *(float2*)(orow + ED + e) = make_float2(ad0, ad1);
                *(float2*)(orow + 2 * ED + e) = make_float2(uv.x * ad0, uv.y * ad1);
                *(float2*)(orow + 3 * ED + e) = make_float2(uv.x * aq0, uv.y * aq1);
            }
        }
    }
}

// ---------------------------------------------------------------------------
extern "C" void kernel_launch(void* const* d_in, const int* in_sizes, int n_in,
                              void* d_out, int out_size) {
    const float* Uq   = (const float*)d_in[0];
    const float* Uid  = (const float*)d_in[1];
    const float* mask = (const float*)d_in[2];
    const float* Wcw  = (const float*)d_in[3];
    const float* Wcb  = (const float*)d_in[4];
    float* out = (float*)d_out;

    constexpr int SM_E = 3 * STG_E * 2 + 8 * 128 * 4;  // 65536
    constexpr int SM_T = 3 * STG_T * 2;                // 39936
    constexpr int SM_F = 3 * STG_F * 2;                // 67584
    cudaFuncSetAttribute(e_kernel, cudaFuncAttributeMaxDynamicSharedMemorySize, SM_E);
    cudaFuncSetAttribute(tn_kernel, cudaFuncAttributeMaxDynamicSharedMemorySize, SM_T);
    cudaFuncSetAttribute(nnf_kernel, cudaFuncAttributeMaxDynamicSharedMemorySize, SM_F);

    prep_kernel<<<NB * SL / 8, 256>>>(Uq, Uid, Wcw);
    e_kernel<<<dim3(NB, SL / 128, SL / 128), NTH, SM_E>>>(mask, Wcb);
    colsum_scale_kernel<<<NB * SL / 256, 256>>>(Uq);
    tn_kernel<<<dim3(NB, SL / 64), NTH, SM_T>>>();
    nnf_kernel<<<dim3(NB, SL / 64), NTH, SM_F>>>(Uid, out);
}

// round 8
// speedup vs baseline: 5.7216x; 1.0277x over previous
#include <cuda_runtime.h>
#include <cuda_fp16.h>

constexpr int NB = 8, SL = 2048, ED = 128;
constexpr int BKH = 32;      // k-tile (elements)
constexpr int NTH = 256;
constexpr int NCH = 16;      // SL/128 column-sum chunks
// smem row strides (halves); 16*odd byte strides -> conflict-free LDSM
constexpr int PADE = 40;     // [m][32] tiles (80 B)
constexpr int PADT = 72;     // [k][64] tiles (144 B)
constexpr int PADB = 136;    // [k][128] tiles (272 B)

constexpr int SA_E = 128 * PADE;            // 5120 halves
constexpr int STG_E = 2 * SA_E;             // 10240
constexpr int SA_T = 32 * PADT;             // 2304 (E^T tile [k][64])
constexpr int SB_T = 32 * PADB;             // 4352 (Uid  tile [k][128])
constexpr int STG_T = SA_T + SB_T;          // 6656
constexpr int SA_F = 64 * PADE;             // 2560 (E tile [m=64][k=32])
constexpr int SB_F = 32 * PADB;             // 4352 ([k=32][n=128])
constexpr int STG_F = SA_F + 2 * SB_F;      // 11264

__device__ __half g_EH[(size_t)NB * SL * SL];   // exp(S), fp16 (64 MiB)
__device__ float g_c[NB * SL];
__device__ float g_cpart[NB * NCH * SL];
__device__ float g_sid[NB * SL];
__device__ float g_sq[NB * SL];
__device__ __half g_UidwH[NB * SL * ED];  // rn(Uid .* w_mul)
__device__ __half g_UqrH[NB * SL * ED];   // rn(Uq)
__device__ __half g_UidrH[NB * SL * ED];  // rn(Uid)
__device__ __half g_UqsH[NB * SL * ED];   // rn(Uq / c * 1024)
__device__ __half g_TsH[NB * SL * ED];    // rn((E^T Uid) / c^2 * 1024)

// ---------------------------------------------------------------------------
__device__ __forceinline__ void mma16(float* c, unsigned a0, unsigned a1, unsigned a2,
                                      unsigned a3, unsigned b0, unsigned b1) {
    asm volatile(
        "mma.sync.aligned.m16n8k16.row.col.f32.f16.f16.f32 "
        "{%0,%1,%2,%3},{%4,%5,%6,%7},{%8,%9},{%0,%1,%2,%3};"
        : "+f"(c[0]), "+f"(c[1]), "+f"(c[2]), "+f"(c[3])
        : "r"(a0), "r"(a1), "r"(a2), "r"(a3), "r"(b0), "r"(b1));
}
__device__ __forceinline__ void ldsm4(unsigned& r0, unsigned& r1, unsigned& r2,
                                      unsigned& r3, unsigned a) {
    asm volatile("ldmatrix.sync.aligned.m8n8.x4.shared.b16 {%0,%1,%2,%3},[%4];"
                 : "=r"(r0), "=r"(r1), "=r"(r2), "=r"(r3) : "r"(a));
}
__device__ __forceinline__ void ldsm4t(unsigned& r0, unsigned& r1, unsigned& r2,
                                       unsigned& r3, unsigned a) {
    asm volatile("ldmatrix.sync.aligned.m8n8.x4.trans.shared.b16 {%0,%1,%2,%3},[%4];"
                 : "=r"(r0), "=r"(r1), "=r"(r2), "=r"(r3) : "r"(a));
}
__device__ __forceinline__ void cpa16(unsigned dst, const void* src) {
    asm volatile("cp.async.cg.shared.global [%0], [%1], 16;" :: "r"(dst), "l"(src));
}
__device__ __forceinline__ void cpcommit() { asm volatile("cp.async.commit_group;"); }
template <int N> __device__ __forceinline__ void cpwait() {
    asm volatile("cp.async.wait_group %0;" :: "n"(N));
}
__device__ __forceinline__ unsigned smaddr(const void* p) {
    return (unsigned)__cvta_generic_to_shared(p);
}

// ---------------------------------------------------------------------------
// prep: s_id, s_q (fp32), plus fp16 operand copies
// ---------------------------------------------------------------------------
__global__ void prep_kernel(const float* __restrict__ Uq,
                            const float* __restrict__ Uid,
                            const float* __restrict__ Wc_w) {
    int gw = (blockIdx.x * blockDim.x + threadIdx.x) >> 5;
    int lane = threadIdx.x & 31;
    if (gw >= NB * SL) return;
    float4 a  = reinterpret_cast<const float4*>(Uid + (size_t)gw * ED)[lane];
    float4 q  = reinterpret_cast<const float4*>(Uq + (size_t)gw * ED)[lane];
    float4 w1 = reinterpret_cast<const float4*>(Wc_w)[lane];
    float4 w2 = reinterpret_cast<const float4*>(Wc_w + ED)[lane];
    float4 w3 = reinterpret_cast<const float4*>(Wc_w + 2 * ED)[lane];
    float s1 = a.x * w1.x + a.y * w1.y + a.z * w1.z + a.w * w1.w;
    float s2 = q.x * w2.x + q.y * w2.y + q.z * w2.z + q.w * w2.w;
    #pragma unroll
    for (int o = 16; o > 0; o >>= 1) {
        s1 += __shfl_xor_sync(0xffffffffu, s1, o);
        s2 += __shfl_xor_sync(0xffffffffu, s2, o);
    }
    if (lane == 0) { g_sid[gw] = s1; g_sq[gw] = s2; }
    __half2* d1 = (__half2*)(g_UidwH + (size_t)gw * ED);
    __half2* d2 = (__half2*)(g_UqrH  + (size_t)gw * ED);
    __half2* d3 = (__half2*)(g_UidrH + (size_t)gw * ED);
    d1[lane * 2]     = __floats2half2_rn(a.x * w3.x, a.y * w3.y);
    d1[lane * 2 + 1] = __floats2half2_rn(a.z * w3.z, a.w * w3.w);
    d2[lane * 2]     = __floats2half2_rn(q.x, q.y);
    d2[lane * 2 + 1] = __floats2half2_rn(q.z, q.w);
    d3[lane * 2]     = __floats2half2_rn(a.x, a.y);
    d3[lane * 2 + 1] = __floats2half2_rn(a.z, a.w);
}

// ---------------------------------------------------------------------------
// e_kernel: E = rn_fp16(exp((s_mul+s_id+s_q+b)*mask)) + fused column partials
// A = Uidw [m][k], B = Uqr [n][k], both fp16, non-trans ldsm
// ---------------------------------------------------------------------------
__global__ void __launch_bounds__(NTH, 2)
e_kernel(const float* __restrict__ mask, const float* __restrict__ Wc_b) {
    extern __shared__ __half smh[];
    int b = blockIdx.x, j0 = blockIdx.y * 128, i0 = blockIdx.z * 128;
    const __half* Ap = g_UidwH + (size_t)b * SL * ED;
    const __half* Bp = g_UqrH + (size_t)b * SL * ED;
    int tid = threadIdx.x, lane = tid & 31, wid = tid >> 5;
    int wm_ = wid & 3, wn_ = wid >> 2;  // 4 m-warps x 2 n-warps; warp tile 32x64
    float acc[2][8][4] = {};

    auto stage = [&](int s, int kk) {
        __half* As = smh + s * STG_E;
        __half* Bs = As + SA_E;
        unsigned ab = smaddr(As), bb = smaddr(Bs);
        #pragma unroll
        for (int p = 0; p < 2; p++) {
            int idx = tid + p * NTH;
            int r = idx >> 2, c = (idx & 3) * 8;
            cpa16(ab + (unsigned)(r * PADE + c) * 2u, Ap + (size_t)(i0 + r) * ED + kk + c);
            cpa16(bb + (unsigned)(r * PADE + c) * 2u, Bp + (size_t)(j0 + r) * ED + kk + c);
        }
    };
    auto compute = [&](int s) {
        unsigned abase = smaddr(smh + s * STG_E);
        unsigned bbase = abase + SA_E * 2;
        #pragma unroll
        for (int kc = 0; kc < BKH; kc += 16) {
            int col = kc + ((lane >> 4) & 1) * 8;
            unsigned af[2][4];
            #pragma unroll
            for (int mt = 0; mt < 2; mt++) {
                int row = wm_ * 32 + mt * 16 + (lane & 7) + ((lane >> 3) & 1) * 8;
                ldsm4(af[mt][0], af[mt][1], af[mt][2], af[mt][3],
                      abase + (unsigned)(row * PADE + col) * 2u);
            }
            #pragma unroll
            for (int np = 0; np < 4; np++) {
                int row = wn_ * 64 + np * 16 + (lane & 7) + ((lane >> 3) & 1) * 8;
                unsigned r0, r1, r2, r3;
                ldsm4(r0, r1, r2, r3, bbase + (unsigned)(row * PADE + col) * 2u);
                #pragma unroll
                for (int mt = 0; mt < 2; mt++) {
                    mma16(acc[mt][np * 2 + 0], af[mt][0], af[mt][1], af[mt][2], af[mt][3], r0, r2);
                    mma16(acc[mt][np * 2 + 1], af[mt][0], af[mt][1], af[mt][2], af[mt][3], r1, r3);
                }
            }
        }
    };

    constexpr int NT = ED / BKH;  // 4
    stage(0, 0); cpcommit();
    stage(1, BKH); cpcommit();
    for (int t = 0; t < NT; t++) {
        cpwait<1>();
        __syncthreads();
        compute(t % 3);
        if (t + 2 < NT) stage((t + 2) % 3, (t + 2) * BKH);
        cpcommit();
    }

    float bias = Wc_b[0];
    __half* Eout = g_EH + (size_t)b * SL * SL;
    int r0 = lane >> 2, cc = (lane & 3) * 2;
    float csum[8][2];
    #pragma unroll
    for (int nt = 0; nt < 8; nt++) { csum[nt][0] = 0.f; csum[nt][1] = 0.f; }
    #pragma unroll
    for (int mt = 0; mt < 2; mt++) {
        #pragma unroll
        for (int half_ = 0; half_ < 2; half_++) {
            int i = i0 + wm_ * 32 + mt * 16 + r0 + half_ * 8;
            float si = g_sid[b * SL + i] + bias;
            const float* mrow = mask + (size_t)i * SL;
            __half* erow = Eout + (size_t)i * SL;
            #pragma unroll
            for (int nt = 0; nt < 8; nt++) {
                int j = j0 + wn_ * 64 + nt * 8 + cc;
                float2 mk = __ldg((const float2*)(mrow + j));
                float2 sq2 = *(const float2*)(&g_sq[b * SL + j]);
                __half h0 = __float2half_rn(__expf((acc[mt][nt][half_ * 2 + 0] + si + sq2.x) * mk.x));
                __half h1 = __float2half_rn(__expf((acc[mt][nt][half_ * 2 + 1] + si + sq2.y) * mk.y));
                *(__half2*)(erow + j) = __halves2half2(h0, h1);
                csum[nt][0] += __half2float(h0);
                csum[nt][1] += __half2float(h1);
            }
        }
    }
    #pragma unroll
    for (int nt = 0; nt < 8; nt++) {
        #pragma unroll
        for (int d = 0; d < 2; d++) {
            float v = csum[nt][d];
            v += __shfl_xor_sync(0xffffffffu, v, 4);
            v += __shfl_xor_sync(0xffffffffu, v, 8);
            v += __shfl_xor_sync(0xffffffffu, v, 16);
            csum[nt][d] = v;
        }
    }
    float* red = (float*)(smh + 3 * STG_E);
    if (lane < 4) {
        #pragma unroll
        for (int nt = 0; nt < 8; nt++) {
            red[wid * 128 + wn_ * 64 + nt * 8 + lane * 2 + 0] = csum[nt][0];
            red[wid * 128 + wn_ * 64 + nt * 8 + lane * 2 + 1] = csum[nt][1];
        }
    }
    __syncthreads();
    if (tid < 128) {
        int g = (tid >> 6) * 4;
        float s = red[(g + 0) * 128 + tid] + red[(g + 1) * 128 + tid] +
                  red[(g + 2) * 128 + tid] + red[(g + 3) * 128 + tid];
        g_cpart[((size_t)b * NCH + blockIdx.z) * SL + j0 + tid] = s;
    }
}

// ---------------------------------------------------------------------------
// colsum finish + Uqs' = rn_fp16(Uq / c * 1024): 256 blocks x 64 rows
// ---------------------------------------------------------------------------
__global__ void __launch_bounds__(256)
colsum_scale_kernel(const float* __restrict__ Uq) {
    __shared__ float rcs[64];
    int tid = threadIdx.x;
    int base = blockIdx.x * 64;
    if (tid < 64) {
        int idx = base + tid;
        int b = idx / SL, j = idx % SL;
        float s = 0.f;
        #pragma unroll
        for (int ch = 0; ch < NCH; ch++) s += g_cpart[((size_t)b * NCH + ch) * SL + j];
        g_c[idx] = s;
        rcs[tid] = 1024.0f / s;
    }
    __syncthreads();
    #pragma unroll
    for (int it = 0; it < 8; it++) {
        int flat = it * 256 + tid;           // 64 rows x 32 float4
        int rl = flat >> 5, e4 = flat & 31;
        int row = base + rl;
        float rc = rcs[rl];
        float4 v = reinterpret_cast<const float4*>(Uq + (size_t)row * ED)[e4];
        __half2* op = (__half2*)(g_UqsH + (size_t)row * ED);
        op[e4 * 2]     = __floats2half2_rn(v.x * rc, v.y * rc);
        op[e4 * 2 + 1] = __floats2half2_rn(v.z * rc, v.w * rc);
    }
}

// ---------------------------------------------------------------------------
// TN: Ts'[j,e] = rn_fp16( (sum_i E[i,j]*Uid[i,e]) * 1024 / c[j]^2 )
// 4-stage cp.async, 3 CTAs/SM; A = E^T ldsm.trans; B = Uidr ldsm.trans
// ---------------------------------------------------------------------------
__global__ void __launch_bounds__(NTH, 3)
tn_kernel() {
    extern __shared__ __half smh[];
    int b = blockIdx.x, j0 = blockIdx.y * 64;
    const __half* Ap = g_EH + (size_t)b * SL * SL;
    const __half* Bp = g_UidrH + (size_t)b * SL * ED;
    int tid = threadIdx.x, lane = tid & 31, wid = tid >> 5;
    int wm_ = wid & 1, wn_ = wid >> 1;
    float acc[2][4][4] = {};

    auto stage = [&](int s, int kk) {
        __half* As = smh + s * STG_T;      // [k=32][m=64] stride 72
        __half* Bs = As + SA_T;            // [k=32][n=128] stride 136
        unsigned ab = smaddr(As), bb = smaddr(Bs);
        #pragma unroll
        for (int p = 0; p < 3; p++) {
            int idx = tid + p * NTH;       // 768: 256 A + 512 B
            if (idx < 256) {
                int r = idx >> 3, c = (idx & 7) * 8;
                cpa16(ab + (unsigned)(r * PADT + c) * 2u,
                      Ap + (size_t)(kk + r) * SL + j0 + c);
            } else {
                int q = idx - 256;
                int r = q >> 4, c = (q & 15) * 8;
                cpa16(bb + (unsigned)(r * PADB + c) * 2u,
                      Bp + (size_t)(kk + r) * ED + c);
            }
        }
    };
    auto compute = [&](int s) {
        unsigned abase = smaddr(smh + s * STG_T);
        unsigned bbase = abase + SA_T * 2;
        #pragma unroll
        for (int kc = 0; kc < BKH; kc += 16) {
            unsigned af[2][4];
            #pragma unroll
            for (int mt = 0; mt < 2; mt++) {
                int row = kc + ((lane >> 4) & 1) * 8 + (lane & 7);
                int col = wm_ * 32 + mt * 16 + ((lane >> 3) & 1) * 8;
                ldsm4t(af[mt][0], af[mt][1], af[mt][2], af[mt][3],
                       abase + (unsigned)(row * PADT + col) * 2u);
            }
            #pragma unroll
            for (int np = 0; np < 2; np++) {
                int row = kc + ((lane >> 3) & 1) * 8 + (lane & 7);
                int col = wn_ * 32 + np * 16 + ((lane >> 4) & 1) * 8;
                unsigned r0, r1, r2, r3;
                ldsm4t(r0, r1, r2, r3, bbase + (unsigned)(row * PADB + col) * 2u);
                #pragma unroll
                for (int mt = 0; mt < 2; mt++) {
                    mma16(acc[mt][np * 2 + 0], af[mt][0], af[mt][1], af[mt][2], af[mt][3], r0, r1);
                    mma16(acc[mt][np * 2 + 1], af[mt][0], af[mt][1], af[mt][2], af[mt][3], r2, r3);
                }
            }
        }
    };

    constexpr int NT = SL / BKH;  // 64
    stage(0, 0); cpcommit();
    stage(1, BKH); cpcommit();
    stage(2, 2 * BKH); cpcommit();
    for (int t = 0; t < NT; t++) {
        cpwait<2>();
        __syncthreads();
        compute(t & 3);
        if (t + 3 < NT) stage((t + 3) & 3, (t + 3) * BKH);
        cpcommit();
    }

    int r0 = lane >> 2, cc = (lane & 3) * 2;
    #pragma unroll
    for (int mt = 0; mt < 2; mt++) {
        #pragma unroll
        for (int half_ = 0; half_ < 2; half_++) {
            int j = j0 + wm_ * 32 + mt * 16 + r0 + half_ * 8;
            float cj = g_c[b * SL + j];
            float s = 1024.0f / (cj * cj);
            __half* orow = g_TsH + ((size_t)b * SL + j) * ED;
            #pragma unroll
            for (int nt = 0; nt < 4; nt++) {
                int e = wn_ * 32 + nt * 8 + cc;
                *(__half2*)(orow + e) = __floats2half2_rn(acc[mt][nt][half_ * 2] * s,
                                                          acc[mt][nt][half_ * 2 + 1] * s);
            }
        }
    }
}

// ---------------------------------------------------------------------------
// Fused NN: acc0 = E@Uqs', acc1 = E@Ts' (one E pass), assembled output /1024
// 4-stage cp.async; streaming stores for output (keep E resident in L2)
// ---------------------------------------------------------------------------
__global__ void __launch_bounds__(NTH, 2)
nnf_kernel(const float* __restrict__ Uid, float* __restrict__ outp) {
    extern __shared__ __half smh[];
    int b = blockIdx.x, i0 = blockIdx.y * 64;
    const __half* Ap = g_EH + (size_t)b * SL * SL;
    const __half* B0p = g_UqsH + (size_t)b * SL * ED;
    const __half* B1p = g_TsH + (size_t)b * SL * ED;
    int tid = threadIdx.x, lane = tid & 31, wid = tid >> 5;
    int wm_ = wid & 1, wn_ = wid >> 1;
    float acc0[2][4][4] = {};
    float acc1[2][4][4] = {};

    auto stage = [&](int s, int kk) {
        __half* As = smh + s * STG_F;       // [m=64][k=32] stride 40
        __half* Bs0 = As + SA_F;            // [k=32][n=128] stride 136
        __half* Bs1 = Bs0 + SB_F;
        unsigned ab = smaddr(As), b0 = smaddr(Bs0), b1 = smaddr(Bs1);
        #pragma unroll
        for (int p = 0; p < 5; p++) {
            int idx = tid + p * NTH;        // 1280: 256 A + 512 B0 + 512 B1
            if (idx < 256) {
                int r = idx >> 2, c = (idx & 3) * 8;
                cpa16(ab + (unsigned)(r * PADE + c) * 2u,
                      Ap + (size_t)(i0 + r) * SL + kk + c);
            } else {
                int q = (idx - 256) & 511;
                int r = q >> 4, c = (q & 15) * 8;
                unsigned dst = (idx < 768 ? b0 : b1) + (unsigned)(r * PADB + c) * 2u;
                const __half* src = (idx < 768 ? B0p : B1p) + (size_t)(kk + r) * ED + c;
                cpa16(dst, src);
            }
        }
    };
    auto compute = [&](int s) {
        unsigned abase = smaddr(smh + s * STG_F);
        unsigned b0base = abase + SA_F * 2;
        unsigned b1base = b0base + SB_F * 2;
        #pragma unroll
        for (int kc = 0; kc < BKH; kc += 16) {
            unsigned af[2][4];
            #pragma unroll
            for (int mt = 0; mt < 2; mt++) {
                int row = wm_ * 32 + mt * 16 + (lane & 7) + ((lane >> 3) & 1) * 8;
                int col = kc + ((lane >> 4) & 1) * 8;
                ldsm4(af[mt][0], af[mt][1], af[mt][2], af[mt][3],
                      abase + (unsigned)(row * PADE + col) * 2u);
            }
            #pragma unroll
            for (int np = 0; np < 2; np++) {
                int row = kc + ((lane >> 3) & 1) * 8 + (lane & 7);
                int col = wn_ * 32 + np * 16 + ((lane >> 4) & 1) * 8;
                unsigned r0, r1, r2, r3;
                ldsm4t(r0, r1, r2, r3, b0base + (unsigned)(row * PADB + col) * 2u);
                #pragma unroll
                for (int mt = 0; mt < 2; mt++) {
                    mma16(acc0[mt][np * 2 + 0], af[mt][0], af[mt][1], af[mt][2], af[mt][3], r0, r1);
                    mma16(acc0[mt][np * 2 + 1], af[mt][0], af[mt][1], af[mt][2], af[mt][3], r2, r3);
                }
                ldsm4t(r0, r1, r2, r3, b1base + (unsigned)(row * PADB + col) * 2u);
                #pragma unroll
                for (int mt = 0; mt < 2; mt++) {
                    mma16(acc1[mt][np * 2 + 0], af[mt][0], af[mt][1], af[mt][2], af[mt][3], r0, r1);
                    mma16(acc1[mt][np * 2 + 1], af[mt][0], af[mt][1], af[mt][2], af[mt][3], r2, r3);
                }
            }
        }
    };

    constexpr int NT = SL / BKH;  // 64
    stage(0, 0); cpcommit();
    stage(1, BKH); cpcommit();
    stage(2, 2 * BKH); cpcommit();
    for (int t = 0; t < NT; t++) {
        cpwait<2>();
        __syncthreads();
        compute(t & 3);
        if (t + 3 < NT) stage((t + 3) & 3, (t + 3) * BKH);
        cpcommit();
    }

    constexpr float INV = 1.0f / 1024.0f;
    int r0 = lane >> 2, cc = (lane & 3) * 2;
    #pragma unroll
    for (int mt = 0; mt < 2; mt++) {
        #pragma unroll
        for (int half_ = 0; half_ < 2; half_++) {
            int i = i0 + wm_ * 32 + mt * 16 + r0 + half_ * 8;
            size_t row = (size_t)b * SL + i;
            const float* uidr = Uid + row * ED;
            float* orow = outp + row * (4 * ED);
            #pragma unroll
            for (int nt = 0; nt < 4; nt++) {
                int e = wn_ * 32 + nt * 8 + cc;
                float2 uv = *(const float2*)(uidr + e);
                float ad0 = acc0[mt][nt][half_ * 2] * INV, ad1 = acc0[mt][nt][half_ * 2 + 1] * INV;
                float aq0 = acc1[mt][nt][half_ * 2] * INV, aq1 = acc1[mt][nt][half_ * 2 + 1] * INV;
                __stcs((float2*)(orow + e), uv);
                __stcs((float2*)(orow + ED + e), make_float2(ad0, ad1));
                __stcs((float2*)(orow + 2 * ED + e), make_float2(uv.x * ad0, uv.y * ad1));
                __stcs((float2*)(orow + 3 * ED + e), make_float2(uv.x * aq0, uv.y * aq1));
            }
        }
    }
}

// ---------------------------------------------------------------------------
extern "C" void kernel_launch(void* const* d_in, const int* in_sizes, int n_in,
                              void* d_out, int out_size) {
    const float* Uq   = (const float*)d_in[0];
    const float* Uid  = (const float*)d_in[1];
    const float* mask = (const float*)d_in[2];
    const float* Wcw  = (const float*)d_in[3];
    const float* Wcb  = (const float*)d_in[4];
    float* out = (float*)d_out;

    constexpr int SM_E = 3 * STG_E * 2 + 8 * 128 * 4;  // 65536
    constexpr int SM_T = 4 * STG_T * 2;                // 53248
    constexpr int SM_F = 4 * STG_F * 2;                // 90112
    cudaFuncSetAttribute(e_kernel, cudaFuncAttributeMaxDynamicSharedMemorySize, SM_E);
    cudaFuncSetAttribute(tn_kernel, cudaFuncAttributeMaxDynamicSharedMemorySize, SM_T);
    cudaFuncSetAttribute(nnf_kernel, cudaFuncAttributeMaxDynamicSharedMemorySize, SM_F);

    prep_kernel<<<NB * SL / 8, 256>>>(Uq, Uid, Wcw);
    e_kernel<<<dim3(NB, SL / 128, SL / 128), NTH, SM_E>>>(mask, Wcb);
    colsum_scale_kernel<<<NB * SL / 64, 256>>>(Uq);
    tn_kernel<<<dim3(NB, SL / 64), NTH, SM_T>>>();
    nnf_kernel<<<dim3(NB, SL / 64), NTH, SM_F>>>(Uid, out);
}